// round 15
// baseline (speedup 1.0000x reference)
#include <cuda_runtime.h>
#include <cuda_bf16.h>
#include <math.h>
#include <stdint.h>

// Problem constants
#define BATCH   128
#define NPATH   64
#define PLEN    128
#define DIMV    512
#define NSTATE  16
#define DEPTHN  2
#define DINV    1024
#define DTRV    32
#define NCLS    32
#define SEQ     64
#define ROWSZ   (BATCH*SEQ)        // 8192
#define XZW     (2*DINV)           // 2048
#define HEADK   (NPATH*DIMV)       // 32768
#define HSLABS  64
#define XSLABS  4                  // x_proj split-K factor

// ---------------- scratch (static device globals; no allocation) -------------
__device__ float  g_x[(size_t)ROWSZ*DIMV];
__device__ float  g_xz[(size_t)ROWSZ*XZW];
__device__ float  g_xdbl[(size_t)XSLABS*ROWSZ*64];
__device__ float2 g_stats[BATCH];
__device__ float  g_hpart[(size_t)HSLABS*BATCH*NCLS];
// bf16 hi/lo activation pairs: pair A (x / uc), pair B (scan y)
__device__ __nv_bfloat16 g_ah[(size_t)ROWSZ*DINV];
__device__ __nv_bfloat16 g_al[(size_t)ROWSZ*DINV];
__device__ __nv_bfloat16 g_bh[(size_t)ROWSZ*DINV];
__device__ __nv_bfloat16 g_bl[(size_t)ROWSZ*DINV];
// bf16 hi/lo weight pairs (split once up-front)
__device__ __nv_bfloat16 g_wih[(size_t)DEPTHN*XZW*DIMV];
__device__ __nv_bfloat16 g_wil[(size_t)DEPTHN*XZW*DIMV];
__device__ __nv_bfloat16 g_wxh[(size_t)DEPTHN*64*DINV];
__device__ __nv_bfloat16 g_wxl[(size_t)DEPTHN*64*DINV];
__device__ __nv_bfloat16 g_woh[(size_t)DEPTHN*DIMV*DINV];
__device__ __nv_bfloat16 g_wol[(size_t)DEPTHN*DIMV*DINV];
// seg weights transposed [n][d][p] hi/lo, series hi/lo
__device__ __nv_bfloat16 g_swh[(size_t)NPATH*DIMV*PLEN];
__device__ __nv_bfloat16 g_swl[(size_t)NPATH*DIMV*PLEN];
__device__ __nv_bfloat16 g_srh[(size_t)BATCH*NPATH*PLEN];
__device__ __nv_bfloat16 g_srl[(size_t)BATCH*NPATH*PLEN];

__device__ __forceinline__ float softplusf(float x) {
    return fmaxf(x, 0.0f) + log1pf(expf(-fabsf(x)));
}

__device__ __forceinline__ void cvt_hl(float4 v, uint2& hw, uint2& lw) {
    float f[4] = {v.x, v.y, v.z, v.w};
    unsigned short h[4], l[4];
    #pragma unroll
    for (int i = 0; i < 4; i++) {
        __nv_bfloat16 hb = __float2bfloat16_rn(f[i]);
        h[i] = __bfloat16_as_ushort(hb);
        float r = f[i] - __bfloat162float(hb);
        l[i] = __bfloat16_as_ushort(__float2bfloat16_rn(r));
    }
    hw.x = (uint32_t)h[0] | ((uint32_t)h[1] << 16);
    hw.y = (uint32_t)h[2] | ((uint32_t)h[3] << 16);
    lw.x = (uint32_t)l[0] | ((uint32_t)l[1] << 16);
    lw.y = (uint32_t)l[2] | ((uint32_t)l[3] << 16);
}

__device__ __forceinline__ void pack2(float v0, float v1, uint32_t& hw, uint32_t& lw) {
    __nv_bfloat16 h0 = __float2bfloat16_rn(v0);
    __nv_bfloat16 h1 = __float2bfloat16_rn(v1);
    float r0 = v0 - __bfloat162float(h0), r1 = v1 - __bfloat162float(h1);
    hw = (uint32_t)__bfloat16_as_ushort(h0) | ((uint32_t)__bfloat16_as_ushort(h1) << 16);
    lw = (uint32_t)__bfloat16_as_ushort(__float2bfloat16_rn(r0))
       | ((uint32_t)__bfloat16_as_ushort(__float2bfloat16_rn(r1)) << 16);
}

// ---------------- ONE prep kernel: weight splits + seg_w transpose + series --
#define WIN4  (DEPTHN * XZW * DIMV / 4)   // 524288
#define WXN4  (DEPTHN * 64 * DINV / 4)    // 32768
#define WON4  (DEPTHN * DIMV * DINV / 4)  // 262144
#define SPLIT3_N4   (WIN4 + WXN4 + WON4)              // 819200
#define SPLIT3_BLK  (SPLIT3_N4 / 256)                 // 3200
#define TRANS_BLK   ((DIMV/32) * (PLEN/32) * NPATH)   // 4096
#define SER_N4      (BATCH * NPATH * PLEN / 4)        // 262144
#define SER_BLK     (SER_N4 / 256)                    // 1024
#define PREP_BLK    (SPLIT3_BLK + TRANS_BLK + SER_BLK)

__global__ void __launch_bounds__(256) prep_kernel(
    const float* __restrict__ wi, const float* __restrict__ wx,
    const float* __restrict__ wo, const float* __restrict__ segw,
    const float* __restrict__ series)
{
    const int blk = blockIdx.x;
    if (blk < SPLIT3_BLK) {
        int i = blk * 256 + threadIdx.x;
        const float* src; __nv_bfloat16 *hi, *lo; int idx;
        if (i < WIN4)                    { src = wi; hi = g_wih; lo = g_wil; idx = i; }
        else if (i < WIN4 + WXN4)        { src = wx; hi = g_wxh; lo = g_wxl; idx = i - WIN4; }
        else                             { src = wo; hi = g_woh; lo = g_wol; idx = i - WIN4 - WXN4; }
        float4 v = ((const float4*)src)[idx];
        uint2 hw, lw; cvt_hl(v, hw, lw);
        ((uint2*)hi)[idx] = hw;
        ((uint2*)lo)[idx] = lw;
    } else if (blk < SPLIT3_BLK + TRANS_BLK) {
        __shared__ float tile[32][33];
        const int i = blk - SPLIT3_BLK;
        const int d0 = (i & 15) * 32, p0 = ((i >> 4) & 3) * 32, n = i >> 6;
        const int tx = threadIdx.x & 31, ty = threadIdx.x >> 5;
        #pragma unroll
        for (int j = 0; j < 4; j++) {
            int p = p0 + ty + j * 8;
            tile[ty + j * 8][tx] =
                segw[(size_t)n * PLEN * DIMV + (size_t)p * DIMV + d0 + tx];
        }
        __syncthreads();
        #pragma unroll
        for (int j = 0; j < 4; j++) {
            int d = d0 + ty + j * 8;
            float v = tile[tx][ty + j * 8];
            __nv_bfloat16 h = __float2bfloat16_rn(v);
            size_t o = (size_t)n * DIMV * PLEN + (size_t)d * PLEN + p0 + tx;
            g_swh[o] = h;
            g_swl[o] = __float2bfloat16_rn(v - __bfloat162float(h));
        }
    } else {
        int idx = (blk - SPLIT3_BLK - TRANS_BLK) * 256 + threadIdx.x;
        float4 v = ((const float4*)series)[idx];
        uint2 hw, lw; cvt_hl(v, hw, lw);
        ((uint2*)g_srh)[idx] = hw;
        ((uint2*)g_srl)[idx] = lw;
    }
}

__device__ __forceinline__ void mma16816(float* c, const uint32_t* a, const uint32_t* b) {
    asm volatile(
        "mma.sync.aligned.m16n8k16.row.col.f32.bf16.bf16.f32 "
        "{%0,%1,%2,%3}, {%4,%5,%6,%7}, {%8,%9}, {%0,%1,%2,%3};"
        : "+f"(c[0]), "+f"(c[1]), "+f"(c[2]), "+f"(c[3])
        : "r"(a[0]), "r"(a[1]), "r"(a[2]), "r"(a[3]), "r"(b[0]), "r"(b[1]));
}
__device__ __forceinline__ void ldsm4(uint32_t* r, uint32_t addr) {
    asm volatile("ldmatrix.sync.aligned.m8n8.x4.shared.b16 {%0,%1,%2,%3}, [%4];"
        : "=r"(r[0]), "=r"(r[1]), "=r"(r[2]), "=r"(r[3]) : "r"(addr));
}
__device__ __forceinline__ void cp16(uint32_t dst, const void* src) {
    asm volatile("cp.async.cg.shared.global [%0], [%1], 16;" :: "r"(dst), "l"(src));
}
__device__ __forceinline__ void cp_commit() {
    asm volatile("cp.async.commit_group;" ::: "memory");
}
template<int N>
__device__ __forceinline__ void cp_wait() {
    asm volatile("cp.async.wait_group %0;" :: "n"(N) : "memory");
}

// =============== HMMA bf16x3 GEMM (ldmatrix + cp.async pipeline) =============
template<int BM, int BN, int WM, int WN, bool WSPLIT, bool WRITEC>
__global__ void __launch_bounds__(256, 2) hmma_gemm(
    const __nv_bfloat16* __restrict__ Ah, const __nv_bfloat16* __restrict__ Al,
    const __nv_bfloat16* __restrict__ Wh, const __nv_bfloat16* __restrict__ Wl,
    float* __restrict__ C, __nv_bfloat16* __restrict__ Chi,
    __nv_bfloat16* __restrict__ Clo, int M, int N, int K,
    int lda, int ldb, int ldc, int aZ, int wZ, long long cZ, int nsplit)
{
    constexpr int BK = 32, SA = 40;
    constexpr int WTM = BM / WM, WTN = BN / WN;
    constexpr int MF = WTM / 16, NF = WTN / 8;
    static_assert(WM * WN == 8, "8 warps");
    static_assert(NF % 2 == 0, "NF even for paired ldmatrix");
    constexpr int AOFF = 0, ALOFF = BM * SA, WOFF = 2 * BM * SA,
                  WLOFF = 2 * BM * SA + BN * SA;
    constexpr int STG = (2 * BM + 2 * BN) * SA;

    extern __shared__ __nv_bfloat16 smem[];
    uint32_t sbase;
    asm("{ .reg .u64 t; cvta.to.shared.u64 t, %1; cvt.u32.u64 %0, t; }"
        : "=r"(sbase) : "l"(smem));

    const int tid = threadIdx.x, lane = tid & 31, wid = tid >> 5;
    const int warpM = wid % WM, warpN = wid / WM;
    const int m0 = blockIdx.y * BM, n0 = blockIdx.x * BN;
    const int z = blockIdx.z;
    Ah += (size_t)z * aZ;  Al += (size_t)z * aZ;
    Wh += (size_t)z * wZ;  Wl += (size_t)z * wZ;
    C  += (size_t)z * cZ;
    const int Keff  = K / nsplit;
    const int kbase = (nsplit > 1) ? z * Keff : 0;
    const int g = lane >> 2, c2 = (lane & 3) * 2;
    const int mbase = warpM * WTM, nbase = warpN * WTN;

    const int a_row = (lane & 7) | (((lane >> 3) & 1) << 3);
    const int a_kof = ((lane >> 4) & 1) * 8;
    const int b_row = (lane & 7) | (((lane >> 4) & 1) << 3);
    const int b_kof = ((lane >> 3) & 1) * 8;

    float acc[MF][NF][4];
    #pragma unroll
    for (int mi = 0; mi < MF; mi++)
        #pragma unroll
        for (int ni = 0; ni < NF; ni++)
            #pragma unroll
            for (int q = 0; q < 4; q++) acc[mi][ni][q] = 0.f;

    const int NC = Keff / BK;

    auto load_chunk = [&](int c, int s) {
        const int kc = kbase + c * BK;
        const uint32_t st = sbase + (uint32_t)s * STG * 2;
        #pragma unroll
        for (int it = 0; it < (BM * 4 + 255) / 256; it++) {
            int i = tid + it * 256;
            if ((BM * 4) % 256 == 0 || i < BM * 4) {
                int r = i >> 2, q = i & 3;
                uint32_t d = st + (uint32_t)r * 80 + q * 16;
                const size_t go = (size_t)(m0 + r) * lda + kc + q * 8;
                cp16(d + AOFF * 2,  Ah + go);
                cp16(d + ALOFF * 2, Al + go);
            }
        }
        #pragma unroll
        for (int it = 0; it < (BN * 4 + 255) / 256; it++) {
            int i = tid + it * 256;
            if ((BN * 4) % 256 == 0 || i < BN * 4) {
                int r = i >> 2, q = i & 3;
                uint32_t d = st + (uint32_t)r * 80 + q * 16;
                const size_t go = (size_t)(n0 + r) * ldb + kc + q * 8;
                cp16(d + WOFF * 2,  Wh + go);
                cp16(d + WLOFF * 2, Wl + go);
            }
        }
    };

    load_chunk(0, 0);
    cp_commit();

    for (int c = 0; c < NC; c++) {
        const int s = c & 1;
        if (c + 1 < NC) {
            load_chunk(c + 1, (c + 1) & 1);
            cp_commit();
            cp_wait<1>();
        } else {
            cp_wait<0>();
        }
        __syncthreads();

        const uint32_t sb  = sbase + (uint32_t)s * STG * 2;
        const uint32_t pAh = sb + AOFF * 2,  pAl = sb + ALOFF * 2;
        const uint32_t pWh = sb + WOFF * 2,  pWl = sb + WLOFF * 2;

        #pragma unroll
        for (int ks = 0; ks < BK; ks += 16) {
            uint32_t ah[MF][4], al[MF][4], bh[NF][2], bl[NF][2];
            #pragma unroll
            for (int mi = 0; mi < MF; mi++)
                ldsm4(ah[mi], pAh + ((uint32_t)(mbase + mi * 16 + a_row) * SA
                                     + ks + a_kof) * 2);
            #pragma unroll
            for (int ni = 0; ni < NF; ni += 2) {
                uint32_t t[4];
                ldsm4(t, pWh + ((uint32_t)(nbase + ni * 8 + b_row) * SA
                                + ks + b_kof) * 2);
                bh[ni][0] = t[0]; bh[ni][1] = t[1];
                bh[ni + 1][0] = t[2]; bh[ni + 1][1] = t[3];
            }
            #pragma unroll
            for (int mi = 0; mi < MF; mi++)
                #pragma unroll
                for (int ni = 0; ni < NF; ni++)
                    mma16816(acc[mi][ni], ah[mi], bh[ni]);
            #pragma unroll
            for (int ni = 0; ni < NF; ni += 2) {
                uint32_t t[4];
                ldsm4(t, pWl + ((uint32_t)(nbase + ni * 8 + b_row) * SA
                                + ks + b_kof) * 2);
                bl[ni][0] = t[0]; bl[ni][1] = t[1];
                bl[ni + 1][0] = t[2]; bl[ni + 1][1] = t[3];
            }
            #pragma unroll
            for (int mi = 0; mi < MF; mi++)
                #pragma unroll
                for (int ni = 0; ni < NF; ni++)
                    mma16816(acc[mi][ni], ah[mi], bl[ni]);
            #pragma unroll
            for (int mi = 0; mi < MF; mi++)
                ldsm4(al[mi], pAl + ((uint32_t)(mbase + mi * 16 + a_row) * SA
                                     + ks + a_kof) * 2);
            #pragma unroll
            for (int mi = 0; mi < MF; mi++)
                #pragma unroll
                for (int ni = 0; ni < NF; ni++)
                    mma16816(acc[mi][ni], al[mi], bh[ni]);
        }
        __syncthreads();
    }

    #pragma unroll
    for (int mi = 0; mi < MF; mi++) {
        int row = m0 + mbase + mi * 16 + g;
        #pragma unroll
        for (int ni = 0; ni < NF; ni++) {
            int col = n0 + nbase + ni * 8 + c2;
            size_t o0 = (size_t)row * ldc + col;
            size_t o8 = (size_t)(row + 8) * ldc + col;
            if (WRITEC) {
                *(float2*)(C + o0) = make_float2(acc[mi][ni][0], acc[mi][ni][1]);
                *(float2*)(C + o8) = make_float2(acc[mi][ni][2], acc[mi][ni][3]);
            }
            if (WSPLIT) {
                uint32_t hw, lw;
                pack2(acc[mi][ni][0], acc[mi][ni][1], hw, lw);
                *(uint32_t*)(Chi + o0) = hw;
                *(uint32_t*)(Clo + o0) = lw;
                pack2(acc[mi][ni][2], acc[mi][ni][3], hw, lw);
                *(uint32_t*)(Chi + o8) = hw;
                *(uint32_t*)(Clo + o8) = lw;
            }
        }
    }
}

// ------- post-seg LN: warp per row of g_x[8192,512], bias + LN -> pair A -----
__global__ void __launch_bounds__(256) row_ln_kernel(
    const float* __restrict__ segb, const float* __restrict__ lng,
    const float* __restrict__ lnb)
{
    const int wid = threadIdx.x >> 5, lane = threadIdx.x & 31;
    const int row = blockIdx.x * 8 + wid;       // row = b*64 + n
    const int n = row & (NPATH - 1);
    const float* xr = g_x + (size_t)row * DIMV;
    const float* bp = segb + (size_t)n * DIMV;

    float v[16], s = 0.f, sq = 0.f;
    #pragma unroll
    for (int i = 0; i < 16; i++) {
        v[i] = xr[lane + 32 * i] + bp[lane + 32 * i];
        s += v[i]; sq += v[i] * v[i];
    }
    #pragma unroll
    for (int o = 16; o > 0; o >>= 1) {
        s  += __shfl_xor_sync(0xffffffffu, s,  o);
        sq += __shfl_xor_sync(0xffffffffu, sq, o);
    }
    float mu  = s * (1.0f / DIMV);
    float rstd = rsqrtf(sq * (1.0f / DIMV) - mu * mu + 1e-5f);
    #pragma unroll
    for (int i = 0; i < 16; i++) {
        int c = lane + 32 * i;
        float o = (v[i] - mu) * rstd * lng[n * DIMV + c] + lnb[n * DIMV + c];
        size_t idx = (size_t)row * DIMV + c;
        __nv_bfloat16 h = __float2bfloat16_rn(o);
        g_ah[idx] = h;
        g_al[idx] = __float2bfloat16_rn(o - __bfloat162float(h));
    }
}

// ------- conv (k=4, t-marching) + bias + silu -> bf16 hi/lo pair A only ------
__global__ void __launch_bounds__(256) conv_silu_kernel(
    const float* __restrict__ cw, const float* __restrict__ cb)
{
    const int b  = blockIdx.x;
    const int t0 = blockIdx.y * 16;
    const int c4 = threadIdx.x * 4;

    float4 w0 = *(const float4*)(cw + (size_t)(c4 + 0) * 4);
    float4 w1 = *(const float4*)(cw + (size_t)(c4 + 1) * 4);
    float4 w2 = *(const float4*)(cw + (size_t)(c4 + 2) * 4);
    float4 w3 = *(const float4*)(cw + (size_t)(c4 + 3) * 4);
    float4 bias = *(const float4*)(cb + c4);

    const float* ubase = g_xz + (size_t)b * SEQ * XZW + c4;
    float4 um3 = make_float4(0,0,0,0), um2 = um3, um1 = um3;
    if (t0 - 3 >= 0) um3 = *(const float4*)(ubase + (size_t)(t0 - 3) * XZW);
    if (t0 - 2 >= 0) um2 = *(const float4*)(ubase + (size_t)(t0 - 2) * XZW);
    if (t0 - 1 >= 0) um1 = *(const float4*)(ubase + (size_t)(t0 - 1) * XZW);

    #pragma unroll
    for (int tt = 0; tt < 16; tt++) {
        const int t = t0 + tt;
        float4 u = *(const float4*)(ubase + (size_t)t * XZW);
        float4 a;
        a.x = bias.x + um3.x*w0.x + um2.x*w0.y + um1.x*w0.z + u.x*w0.w;
        a.y = bias.y + um3.y*w1.x + um2.y*w1.y + um1.y*w1.z + u.y*w1.w;
        a.z = bias.z + um3.z*w2.x + um2.z*w2.y + um1.z*w2.z + u.z*w2.w;
        a.w = bias.w + um3.w*w3.x + um2.w*w3.y + um1.w*w3.z + u.w*w3.w;
        a.x = a.x / (1.0f + __expf(-a.x));
        a.y = a.y / (1.0f + __expf(-a.y));
        a.z = a.z / (1.0f + __expf(-a.z));
        a.w = a.w / (1.0f + __expf(-a.w));
        size_t o = ((size_t)b * SEQ + t) * DINV + c4;
        uint2 hw, lw; cvt_hl(a, hw, lw);
        *(uint2*)(g_ah + o) = hw;
        *(uint2*)(g_al + o) = lw;
        um3 = um2; um2 = um1; um1 = u;
    }
}

// -------- fused dt_proj + softplus + selective scan + gate -> pair B ---------
__global__ void __launch_bounds__(256) scan_kernel(
    const float* __restrict__ A_log, const float* __restrict__ Dp_,
    const float* __restrict__ wdt,   const float* __restrict__ bdt)
{
    const int b = blockIdx.x;
    const int d = blockIdx.y * 256 + threadIdx.x;
    __shared__ float sB[SEQ][NSTATE];
    __shared__ float sC[SEQ][NSTATE];
    __shared__ float sDT[SEQ][DTRV];

    for (int i = threadIdx.x; i < SEQ * 64; i += 256) {
        int t = i >> 6, j = i & 63;
        size_t base = ((size_t)(b * SEQ + t)) * 64 + j;
        float v = 0.f;
        #pragma unroll
        for (int s = 0; s < XSLABS; s++)
            v += g_xdbl[(size_t)s * ROWSZ * 64 + base];
        if (j < 32)       sDT[t][j] = v;
        else if (j < 48)  sB[t][j - 32] = v;
        else              sC[t][j - 48] = v;
    }
    __syncthreads();

    float w[DTRV];
    #pragma unroll
    for (int q = 0; q < DTRV / 4; q++) {
        float4 v = *(const float4*)(wdt + (size_t)d * DTRV + q * 4);
        w[4*q] = v.x; w[4*q+1] = v.y; w[4*q+2] = v.z; w[4*q+3] = v.w;
    }
    const float bdtv = bdt[d];

    float rA[NSTATE];
    #pragma unroll
    for (int n = 0; n < NSTATE; n++) rA[n] = -expf(A_log[(size_t)d * NSTATE + n]);
    const float Dv = Dp_[d];
    float h[NSTATE];
    #pragma unroll
    for (int n = 0; n < NSTATE; n++) h[n] = 0.f;

    const size_t rowbase = (size_t)b * SEQ;
    for (int t = 0; t < SEQ; t++) {
        const size_t row = rowbase + t;
        float dot = bdtv;
        #pragma unroll
        for (int j = 0; j < DTRV; j++) dot += sDT[t][j] * w[j];
        float delta = softplusf(dot);
        float u = __bfloat162float(g_ah[row * DINV + d])
                + __bfloat162float(g_al[row * DINV + d]);
        float du = delta * u;
        float y = 0.f;
        #pragma unroll
        for (int n = 0; n < NSTATE; n++) {
            float dA = __expf(delta * rA[n]);
            h[n] = dA * h[n] + du * sB[t][n];
            y += h[n] * sC[t][n];
        }
        float z = g_xz[row * XZW + DINV + d];
        float silu_z = z / (1.0f + __expf(-z));
        float yv = (y + u * Dv) * silu_z;
        __nv_bfloat16 hb = __float2bfloat16_rn(yv);
        g_bh[row * DINV + d] = hb;
        g_bl[row * DINV + d] = __float2bfloat16_rn(yv - __bfloat162float(hb));
    }
}

// ---------------- final LayerNorm stats ---------------------------------------
__global__ void __launch_bounds__(256) ln_stats_kernel()
{
    const int b = blockIdx.x;
    const float4* xp = (const float4*)(g_x + (size_t)b * HEADK);
    float s = 0.f, sq = 0.f;
    for (int i = threadIdx.x; i < HEADK / 4; i += 256) {
        float4 v = xp[i];
        s  += v.x + v.y + v.z + v.w;
        sq += v.x*v.x + v.y*v.y + v.z*v.z + v.w*v.w;
    }
    __shared__ float rs[256], rq[256];
    rs[threadIdx.x] = s; rq[threadIdx.x] = sq; __syncthreads();
    for (int st = 128; st > 0; st >>= 1) {
        if (threadIdx.x < st) { rs[threadIdx.x] += rs[threadIdx.x + st];
                                rq[threadIdx.x] += rq[threadIdx.x + st]; }
        __syncthreads();
    }
    if (threadIdx.x == 0) {
        float mu  = rs[0] / (float)HEADK;
        float var = rq[0] / (float)HEADK - mu * mu;
        g_stats[b] = make_float2(mu, rsqrtf(var + 1e-5f));
    }
}

// ---------------- head: split-K GEMM (LN fused on A load) --------------------
__global__ void __launch_bounds__(256) head_gemm_kernel(
    const float* __restrict__ lng, const float* __restrict__ lnb,
    const float* __restrict__ hw)
{
    constexpr int BK = 16;
    const int slab = blockIdx.x;
    const int kbeg = slab * (HEADK / HSLABS);
    __shared__ float sX[BK][BATCH];
    __shared__ float sW[BK][NCLS];
    const int tid = threadIdx.x;
    const int tx = tid & 15;
    const int ty = tid >> 4;

    float acc[8][2];
    #pragma unroll
    for (int i = 0; i < 8; i++) { acc[i][0] = 0.f; acc[i][1] = 0.f; }

    for (int k0 = kbeg; k0 < kbeg + HEADK / HSLABS; k0 += BK) {
        #pragma unroll
        for (int l = 0; l < 2; l++) {
            int idx = tid + l * 256;
            int row = idx >> 2, kq = (idx & 3) << 2;
            float2 st = g_stats[row];
            float4 v  = *(const float4*)(g_x + (size_t)row * HEADK + k0 + kq);
            float4 gg = *(const float4*)(lng + k0 + kq);
            float4 bb = *(const float4*)(lnb + k0 + kq);
            sX[kq + 0][row] = (v.x - st.x) * st.y * gg.x + bb.x;
            sX[kq + 1][row] = (v.y - st.x) * st.y * gg.y + bb.y;
            sX[kq + 2][row] = (v.z - st.x) * st.y * gg.z + bb.z;
            sX[kq + 3][row] = (v.w - st.x) * st.y * gg.w + bb.w;
        }
        if (tid < 128) {
            int row = tid >> 2, kq = (tid & 3) << 2;
            float4 v = *(const float4*)(hw + (size_t)row * HEADK + k0 + kq);
            sW[kq + 0][row] = v.x; sW[kq + 1][row] = v.y;
            sW[kq + 2][row] = v.z; sW[kq + 3][row] = v.w;
        }
        __syncthreads();
        #pragma unroll
        for (int kk = 0; kk < BK; kk++) {
            float w0 = sW[kk][tx * 2], w1 = sW[kk][tx * 2 + 1];
            #pragma unroll
            for (int i = 0; i < 8; i++) {
                float a = sX[kk][ty * 8 + i];
                acc[i][0] += a * w0;
                acc[i][1] += a * w1;
            }
        }
        __syncthreads();
    }
    #pragma unroll
    for (int i = 0; i < 8; i++) {
        int m = ty * 8 + i;
        g_hpart[((size_t)slab * BATCH + m) * NCLS + tx * 2 + 0] = acc[i][0];
        g_hpart[((size_t)slab * BATCH + m) * NCLS + tx * 2 + 1] = acc[i][1];
    }
}

__global__ void __launch_bounds__(256) head_reduce_kernel(
    const float* __restrict__ head_b, float* __restrict__ out)
{
    int idx = blockIdx.x * blockDim.x + threadIdx.x;
    if (idx < BATCH * NCLS) {
        float s = head_b[idx & (NCLS - 1)];
        for (int sl = 0; sl < HSLABS; sl++)
            s += g_hpart[(size_t)sl * BATCH * NCLS + idx];
        out[idx] = s;
    }
}

// ---------------- host orchestration -----------------------------------------
extern "C" void kernel_launch(void* const* d_in, const int* in_sizes, int n_in,
                              void* d_out, int out_size)
{
    const float* series    = (const float*)d_in[0];
    const float* seg_w     = (const float*)d_in[1];
    const float* seg_b     = (const float*)d_in[2];
    const float* ln_g      = (const float*)d_in[3];
    const float* ln_b      = (const float*)d_in[4];
    const float* in_proj_w = (const float*)d_in[5];
    const float* conv_w    = (const float*)d_in[6];
    const float* conv_b    = (const float*)d_in[7];
    const float* x_proj_w  = (const float*)d_in[8];
    const float* dt_proj_w = (const float*)d_in[9];
    const float* dt_proj_b = (const float*)d_in[10];
    const float* A_log     = (const float*)d_in[11];
    const float* Dw        = (const float*)d_in[12];
    const float* out_proj_w= (const float*)d_in[13];
    const float* hlng      = (const float*)d_in[14];
    const float* hlnb      = (const float*)d_in[15];
    const float* head_w    = (const float*)d_in[16];
    const float* head_b    = (const float*)d_in[17];
    float* out = (float*)d_out;

    float *px, *pxz, *pxdbl;
    __nv_bfloat16 *pah, *pal, *pbh, *pbl;
    __nv_bfloat16 *pwih, *pwil, *pwxh, *pwxl, *pwoh, *pwol;
    __nv_bfloat16 *pswh, *pswl, *psrh, *psrl;
    cudaGetSymbolAddress((void**)&px,    g_x);
    cudaGetSymbolAddress((void**)&pxz,   g_xz);
    cudaGetSymbolAddress((void**)&pxdbl, g_xdbl);
    cudaGetSymbolAddress((void**)&pah,   g_ah);
    cudaGetSymbolAddress((void**)&pal,   g_al);
    cudaGetSymbolAddress((void**)&pbh,   g_bh);
    cudaGetSymbolAddress((void**)&pbl,   g_bl);
    cudaGetSymbolAddress((void**)&pwih,  g_wih);
    cudaGetSymbolAddress((void**)&pwil,  g_wil);
    cudaGetSymbolAddress((void**)&pwxh,  g_wxh);
    cudaGetSymbolAddress((void**)&pwxl,  g_wxl);
    cudaGetSymbolAddress((void**)&pwoh,  g_woh);
    cudaGetSymbolAddress((void**)&pwol,  g_wol);
    cudaGetSymbolAddress((void**)&pswh,  g_swh);
    cudaGetSymbolAddress((void**)&pswl,  g_swl);
    cudaGetSymbolAddress((void**)&psrh,  g_srh);
    cudaGetSymbolAddress((void**)&psrl,  g_srl);

    const int SMEM128 = 2 * (2*128 + 2*128) * 40 * 2;  // 81920
    const int SMEM64  = 2 * (2*64  + 2*64 ) * 40 * 2;  // 40960
    cudaFuncSetAttribute((const void*)hmma_gemm<128,128,2,4,false,true>,
                         cudaFuncAttributeMaxDynamicSharedMemorySize, SMEM128);
    cudaFuncSetAttribute((const void*)hmma_gemm<128,128,2,4,true,false>,
                         cudaFuncAttributeMaxDynamicSharedMemorySize, SMEM128);
    cudaFuncSetAttribute((const void*)hmma_gemm<64,64,2,4,false,true>,
                         cudaFuncAttributeMaxDynamicSharedMemorySize, SMEM64);

    // 0) one-time prep: everything in ONE launch
    prep_kernel<<<PREP_BLK, 256>>>(in_proj_w, x_proj_w, out_proj_w, seg_w, series);

    // 1) seg linear: batched over 64 pathways -> g_x fp32
    hmma_gemm<128,128,2,4,false,true><<<dim3(DIMV/128, 1, NPATH), 256, SMEM128>>>(
        psrh, psrl, pswh, pswl, px, nullptr, nullptr,
        BATCH, DIMV, PLEN,
        NPATH*PLEN, PLEN, HEADK, PLEN, DIMV*PLEN, (long long)DIMV, 1);

    // 2) bias + per-pathway LN -> pair A
    row_ln_kernel<<<ROWSZ/8, 256>>>(seg_b, ln_g, ln_b);

    for (int dep = 0; dep < DEPTHN; dep++) {
        // 3) in_proj: [8192,512]x[2048,512]^T -> g_xz (fp32)
        hmma_gemm<128,128,2,4,false,true><<<dim3(XZW/128, ROWSZ/128, 1), 256, SMEM128>>>(
            pah, pal, pwih + (size_t)dep * XZW * DIMV,
            pwil + (size_t)dep * XZW * DIMV, pxz, nullptr, nullptr,
            ROWSZ, XZW, DIMV, DIMV, DIMV, XZW, 0, 0, 0, 1);
        // 4) conv + silu -> pair A (bf16 hi/lo)
        conv_silu_kernel<<<dim3(BATCH, SEQ/16), 256>>>(
            conv_w + (size_t)dep * DINV * 4, conv_b + (size_t)dep * DINV);
        // 5) x_proj split-K x4 -> 4 partial slabs
        hmma_gemm<64,64,2,4,false,true><<<dim3(1, ROWSZ/64, XSLABS), 256, SMEM64>>>(
            pah, pal, pwxh + (size_t)dep * 64 * DINV,
            pwxl + (size_t)dep * 64 * DINV, pxdbl, nullptr, nullptr,
            ROWSZ, 64, DINV, DINV, DINV, 64, 0, 0, (long long)ROWSZ * 64, XSLABS);
        // 6) fused dt_proj + softplus + scan + gate -> pair B
        scan_kernel<<<dim3(BATCH, DINV/256), 256>>>(
            A_log + (size_t)dep * DINV * NSTATE, Dw + (size_t)dep * DINV,
            dt_proj_w + (size_t)dep * DINV * DTRV,
            dt_proj_b + (size_t)dep * DINV);
        // 7) out_proj: depth 0 -> pair A only (fp32 g_x dead);
        //    last depth -> fp32 g_x only (pair A dead)
        if (dep == DEPTHN - 1) {
            hmma_gemm<128,128,2,4,false,true><<<dim3(DIMV/128, ROWSZ/128, 1), 256, SMEM128>>>(
                pbh, pbl, pwoh + (size_t)dep * DIMV * DINV,
                pwol + (size_t)dep * DIMV * DINV, px, nullptr, nullptr,
                ROWSZ, DIMV, DINV, DINV, DINV, DIMV, 0, 0, 0, 1);
        } else {
            hmma_gemm<128,128,2,4,true,false><<<dim3(DIMV/128, ROWSZ/128, 1), 256, SMEM128>>>(
                pbh, pbl, pwoh + (size_t)dep * DIMV * DINV,
                pwol + (size_t)dep * DIMV * DINV, px, pah, pal,
                ROWSZ, DIMV, DINV, DINV, DINV, DIMV, 0, 0, 0, 1);
        }
    }

    // 8) final LN stats + head GEMM + deterministic reduce
    ln_stats_kernel<<<BATCH, 256>>>();
    head_gemm_kernel<<<HSLABS, 256>>>(hlng, hlnb, head_w);
    head_reduce_kernel<<<(BATCH*NCLS + 255)/256, 256>>>(head_b, out);
}

// round 16
// speedup vs baseline: 1.0194x; 1.0194x over previous
#include <cuda_runtime.h>
#include <cuda_bf16.h>
#include <math.h>
#include <stdint.h>

// Problem constants
#define BATCH   128
#define NPATH   64
#define PLEN    128
#define DIMV    512
#define NSTATE  16
#define DEPTHN  2
#define DINV    1024
#define DTRV    32
#define NCLS    32
#define SEQ     64
#define ROWSZ   (BATCH*SEQ)        // 8192
#define XZW     (2*DINV)           // 2048
#define HEADK   (NPATH*DIMV)       // 32768
#define HSLABS  64
#define XSLABS  2                  // x_proj split-K factor (4 retired: R7/R15)

// ---------------- scratch (static device globals; no allocation) -------------
__device__ float  g_x[(size_t)ROWSZ*DIMV];
__device__ float  g_xz[(size_t)ROWSZ*XZW];
__device__ float  g_xdbl[(size_t)XSLABS*ROWSZ*64];
__device__ float2 g_stats[BATCH];
__device__ float  g_hpart[(size_t)HSLABS*BATCH*NCLS];
// bf16 hi/lo activation pairs: pair A (x / uc), pair B (scan y)
__device__ __nv_bfloat16 g_ah[(size_t)ROWSZ*DINV];
__device__ __nv_bfloat16 g_al[(size_t)ROWSZ*DINV];
__device__ __nv_bfloat16 g_bh[(size_t)ROWSZ*DINV];
__device__ __nv_bfloat16 g_bl[(size_t)ROWSZ*DINV];
// bf16 hi/lo weight pairs (split once up-front)
__device__ __nv_bfloat16 g_wih[(size_t)DEPTHN*XZW*DIMV];
__device__ __nv_bfloat16 g_wil[(size_t)DEPTHN*XZW*DIMV];
__device__ __nv_bfloat16 g_wxh[(size_t)DEPTHN*64*DINV];
__device__ __nv_bfloat16 g_wxl[(size_t)DEPTHN*64*DINV];
__device__ __nv_bfloat16 g_woh[(size_t)DEPTHN*DIMV*DINV];
__device__ __nv_bfloat16 g_wol[(size_t)DEPTHN*DIMV*DINV];
// seg weights transposed [n][d][p] hi/lo, series hi/lo
__device__ __nv_bfloat16 g_swh[(size_t)NPATH*DIMV*PLEN];
__device__ __nv_bfloat16 g_swl[(size_t)NPATH*DIMV*PLEN];
__device__ __nv_bfloat16 g_srh[(size_t)BATCH*NPATH*PLEN];
__device__ __nv_bfloat16 g_srl[(size_t)BATCH*NPATH*PLEN];

__device__ __forceinline__ float softplusf(float x) {
    return fmaxf(x, 0.0f) + log1pf(expf(-fabsf(x)));
}

__device__ __forceinline__ void cvt_hl(float4 v, uint2& hw, uint2& lw) {
    float f[4] = {v.x, v.y, v.z, v.w};
    unsigned short h[4], l[4];
    #pragma unroll
    for (int i = 0; i < 4; i++) {
        __nv_bfloat16 hb = __float2bfloat16_rn(f[i]);
        h[i] = __bfloat16_as_ushort(hb);
        float r = f[i] - __bfloat162float(hb);
        l[i] = __bfloat16_as_ushort(__float2bfloat16_rn(r));
    }
    hw.x = (uint32_t)h[0] | ((uint32_t)h[1] << 16);
    hw.y = (uint32_t)h[2] | ((uint32_t)h[3] << 16);
    lw.x = (uint32_t)l[0] | ((uint32_t)l[1] << 16);
    lw.y = (uint32_t)l[2] | ((uint32_t)l[3] << 16);
}

__device__ __forceinline__ void pack2(float v0, float v1, uint32_t& hw, uint32_t& lw) {
    __nv_bfloat16 h0 = __float2bfloat16_rn(v0);
    __nv_bfloat16 h1 = __float2bfloat16_rn(v1);
    float r0 = v0 - __bfloat162float(h0), r1 = v1 - __bfloat162float(h1);
    hw = (uint32_t)__bfloat16_as_ushort(h0) | ((uint32_t)__bfloat16_as_ushort(h1) << 16);
    lw = (uint32_t)__bfloat16_as_ushort(__float2bfloat16_rn(r0))
       | ((uint32_t)__bfloat16_as_ushort(__float2bfloat16_rn(r1)) << 16);
}

// ---------------- ONE prep kernel: weight splits + seg_w transpose + series --
#define WIN4  (DEPTHN * XZW * DIMV / 4)   // 524288
#define WXN4  (DEPTHN * 64 * DINV / 4)    // 32768
#define WON4  (DEPTHN * DIMV * DINV / 4)  // 262144
#define SPLIT3_N4   (WIN4 + WXN4 + WON4)              // 819200
#define SPLIT3_BLK  (SPLIT3_N4 / 256)                 // 3200
#define TRANS_BLK   ((DIMV/32) * (PLEN/32) * NPATH)   // 4096
#define SER_N4      (BATCH * NPATH * PLEN / 4)        // 262144
#define SER_BLK     (SER_N4 / 256)                    // 1024
#define PREP_BLK    (SPLIT3_BLK + TRANS_BLK + SER_BLK)

__global__ void __launch_bounds__(256) prep_kernel(
    const float* __restrict__ wi, const float* __restrict__ wx,
    const float* __restrict__ wo, const float* __restrict__ segw,
    const float* __restrict__ series)
{
    const int blk = blockIdx.x;
    if (blk < SPLIT3_BLK) {
        int i = blk * 256 + threadIdx.x;
        const float* src; __nv_bfloat16 *hi, *lo; int idx;
        if (i < WIN4)                    { src = wi; hi = g_wih; lo = g_wil; idx = i; }
        else if (i < WIN4 + WXN4)        { src = wx; hi = g_wxh; lo = g_wxl; idx = i - WIN4; }
        else                             { src = wo; hi = g_woh; lo = g_wol; idx = i - WIN4 - WXN4; }
        float4 v = ((const float4*)src)[idx];
        uint2 hw, lw; cvt_hl(v, hw, lw);
        ((uint2*)hi)[idx] = hw;
        ((uint2*)lo)[idx] = lw;
    } else if (blk < SPLIT3_BLK + TRANS_BLK) {
        __shared__ float tile[32][33];
        const int i = blk - SPLIT3_BLK;
        const int d0 = (i & 15) * 32, p0 = ((i >> 4) & 3) * 32, n = i >> 6;
        const int tx = threadIdx.x & 31, ty = threadIdx.x >> 5;
        #pragma unroll
        for (int j = 0; j < 4; j++) {
            int p = p0 + ty + j * 8;
            tile[ty + j * 8][tx] =
                segw[(size_t)n * PLEN * DIMV + (size_t)p * DIMV + d0 + tx];
        }
        __syncthreads();
        #pragma unroll
        for (int j = 0; j < 4; j++) {
            int d = d0 + ty + j * 8;
            float v = tile[tx][ty + j * 8];
            __nv_bfloat16 h = __float2bfloat16_rn(v);
            size_t o = (size_t)n * DIMV * PLEN + (size_t)d * PLEN + p0 + tx;
            g_swh[o] = h;
            g_swl[o] = __float2bfloat16_rn(v - __bfloat162float(h));
        }
    } else {
        int idx = (blk - SPLIT3_BLK - TRANS_BLK) * 256 + threadIdx.x;
        float4 v = ((const float4*)series)[idx];
        uint2 hw, lw; cvt_hl(v, hw, lw);
        ((uint2*)g_srh)[idx] = hw;
        ((uint2*)g_srl)[idx] = lw;
    }
}

__device__ __forceinline__ void mma16816(float* c, const uint32_t* a, const uint32_t* b) {
    asm volatile(
        "mma.sync.aligned.m16n8k16.row.col.f32.bf16.bf16.f32 "
        "{%0,%1,%2,%3}, {%4,%5,%6,%7}, {%8,%9}, {%0,%1,%2,%3};"
        : "+f"(c[0]), "+f"(c[1]), "+f"(c[2]), "+f"(c[3])
        : "r"(a[0]), "r"(a[1]), "r"(a[2]), "r"(a[3]), "r"(b[0]), "r"(b[1]));
}
__device__ __forceinline__ void ldsm4(uint32_t* r, uint32_t addr) {
    asm volatile("ldmatrix.sync.aligned.m8n8.x4.shared.b16 {%0,%1,%2,%3}, [%4];"
        : "=r"(r[0]), "=r"(r[1]), "=r"(r[2]), "=r"(r[3]) : "r"(addr));
}
__device__ __forceinline__ void cp16(uint32_t dst, const void* src) {
    asm volatile("cp.async.cg.shared.global [%0], [%1], 16;" :: "r"(dst), "l"(src));
}
__device__ __forceinline__ void cp_commit() {
    asm volatile("cp.async.commit_group;" ::: "memory");
}
template<int N>
__device__ __forceinline__ void cp_wait() {
    asm volatile("cp.async.wait_group %0;" :: "n"(N) : "memory");
}

// =============== HMMA bf16x3 GEMM (ldmatrix + cp.async pipeline) =============
template<int BM, int BN, int WM, int WN, bool WSPLIT, bool WRITEC>
__global__ void __launch_bounds__(256, 2) hmma_gemm(
    const __nv_bfloat16* __restrict__ Ah, const __nv_bfloat16* __restrict__ Al,
    const __nv_bfloat16* __restrict__ Wh, const __nv_bfloat16* __restrict__ Wl,
    float* __restrict__ C, __nv_bfloat16* __restrict__ Chi,
    __nv_bfloat16* __restrict__ Clo, int M, int N, int K,
    int lda, int ldb, int ldc, int aZ, int wZ, long long cZ, int nsplit)
{
    constexpr int BK = 32, SA = 40;
    constexpr int WTM = BM / WM, WTN = BN / WN;
    constexpr int MF = WTM / 16, NF = WTN / 8;
    static_assert(WM * WN == 8, "8 warps");
    static_assert(NF % 2 == 0, "NF even for paired ldmatrix");
    constexpr int AOFF = 0, ALOFF = BM * SA, WOFF = 2 * BM * SA,
                  WLOFF = 2 * BM * SA + BN * SA;
    constexpr int STG = (2 * BM + 2 * BN) * SA;

    extern __shared__ __nv_bfloat16 smem[];
    uint32_t sbase;
    asm("{ .reg .u64 t; cvta.to.shared.u64 t, %1; cvt.u32.u64 %0, t; }"
        : "=r"(sbase) : "l"(smem));

    const int tid = threadIdx.x, lane = tid & 31, wid = tid >> 5;
    const int warpM = wid % WM, warpN = wid / WM;
    const int m0 = blockIdx.y * BM, n0 = blockIdx.x * BN;
    const int z = blockIdx.z;
    Ah += (size_t)z * aZ;  Al += (size_t)z * aZ;
    Wh += (size_t)z * wZ;  Wl += (size_t)z * wZ;
    C  += (size_t)z * cZ;
    const int Keff  = K / nsplit;
    const int kbase = (nsplit > 1) ? z * Keff : 0;
    const int g = lane >> 2, c2 = (lane & 3) * 2;
    const int mbase = warpM * WTM, nbase = warpN * WTN;

    const int a_row = (lane & 7) | (((lane >> 3) & 1) << 3);
    const int a_kof = ((lane >> 4) & 1) * 8;
    const int b_row = (lane & 7) | (((lane >> 4) & 1) << 3);
    const int b_kof = ((lane >> 3) & 1) * 8;

    float acc[MF][NF][4];
    #pragma unroll
    for (int mi = 0; mi < MF; mi++)
        #pragma unroll
        for (int ni = 0; ni < NF; ni++)
            #pragma unroll
            for (int q = 0; q < 4; q++) acc[mi][ni][q] = 0.f;

    const int NC = Keff / BK;

    auto load_chunk = [&](int c, int s) {
        const int kc = kbase + c * BK;
        const uint32_t st = sbase + (uint32_t)s * STG * 2;
        #pragma unroll
        for (int it = 0; it < (BM * 4 + 255) / 256; it++) {
            int i = tid + it * 256;
            if ((BM * 4) % 256 == 0 || i < BM * 4) {
                int r = i >> 2, q = i & 3;
                uint32_t d = st + (uint32_t)r * 80 + q * 16;
                const size_t go = (size_t)(m0 + r) * lda + kc + q * 8;
                cp16(d + AOFF * 2,  Ah + go);
                cp16(d + ALOFF * 2, Al + go);
            }
        }
        #pragma unroll
        for (int it = 0; it < (BN * 4 + 255) / 256; it++) {
            int i = tid + it * 256;
            if ((BN * 4) % 256 == 0 || i < BN * 4) {
                int r = i >> 2, q = i & 3;
                uint32_t d = st + (uint32_t)r * 80 + q * 16;
                const size_t go = (size_t)(n0 + r) * ldb + kc + q * 8;
                cp16(d + WOFF * 2,  Wh + go);
                cp16(d + WLOFF * 2, Wl + go);
            }
        }
    };

    load_chunk(0, 0);
    cp_commit();

    for (int c = 0; c < NC; c++) {
        const int s = c & 1;
        if (c + 1 < NC) {
            load_chunk(c + 1, (c + 1) & 1);
            cp_commit();
            cp_wait<1>();
        } else {
            cp_wait<0>();
        }
        __syncthreads();

        const uint32_t sb  = sbase + (uint32_t)s * STG * 2;
        const uint32_t pAh = sb + AOFF * 2,  pAl = sb + ALOFF * 2;
        const uint32_t pWh = sb + WOFF * 2,  pWl = sb + WLOFF * 2;

        #pragma unroll
        for (int ks = 0; ks < BK; ks += 16) {
            uint32_t ah[MF][4], al[MF][4], bh[NF][2], bl[NF][2];
            #pragma unroll
            for (int mi = 0; mi < MF; mi++)
                ldsm4(ah[mi], pAh + ((uint32_t)(mbase + mi * 16 + a_row) * SA
                                     + ks + a_kof) * 2);
            #pragma unroll
            for (int ni = 0; ni < NF; ni += 2) {
                uint32_t t[4];
                ldsm4(t, pWh + ((uint32_t)(nbase + ni * 8 + b_row) * SA
                                + ks + b_kof) * 2);
                bh[ni][0] = t[0]; bh[ni][1] = t[1];
                bh[ni + 1][0] = t[2]; bh[ni + 1][1] = t[3];
            }
            #pragma unroll
            for (int mi = 0; mi < MF; mi++)
                #pragma unroll
                for (int ni = 0; ni < NF; ni++)
                    mma16816(acc[mi][ni], ah[mi], bh[ni]);
            #pragma unroll
            for (int ni = 0; ni < NF; ni += 2) {
                uint32_t t[4];
                ldsm4(t, pWl + ((uint32_t)(nbase + ni * 8 + b_row) * SA
                                + ks + b_kof) * 2);
                bl[ni][0] = t[0]; bl[ni][1] = t[1];
                bl[ni + 1][0] = t[2]; bl[ni + 1][1] = t[3];
            }
            #pragma unroll
            for (int mi = 0; mi < MF; mi++)
                #pragma unroll
                for (int ni = 0; ni < NF; ni++)
                    mma16816(acc[mi][ni], ah[mi], bl[ni]);
            #pragma unroll
            for (int mi = 0; mi < MF; mi++)
                ldsm4(al[mi], pAl + ((uint32_t)(mbase + mi * 16 + a_row) * SA
                                     + ks + a_kof) * 2);
            #pragma unroll
            for (int mi = 0; mi < MF; mi++)
                #pragma unroll
                for (int ni = 0; ni < NF; ni++)
                    mma16816(acc[mi][ni], al[mi], bh[ni]);
        }
        __syncthreads();
    }

    #pragma unroll
    for (int mi = 0; mi < MF; mi++) {
        int row = m0 + mbase + mi * 16 + g;
        #pragma unroll
        for (int ni = 0; ni < NF; ni++) {
            int col = n0 + nbase + ni * 8 + c2;
            size_t o0 = (size_t)row * ldc + col;
            size_t o8 = (size_t)(row + 8) * ldc + col;
            if (WRITEC) {
                *(float2*)(C + o0) = make_float2(acc[mi][ni][0], acc[mi][ni][1]);
                *(float2*)(C + o8) = make_float2(acc[mi][ni][2], acc[mi][ni][3]);
            }
            if (WSPLIT) {
                uint32_t hw, lw;
                pack2(acc[mi][ni][0], acc[mi][ni][1], hw, lw);
                *(uint32_t*)(Chi + o0) = hw;
                *(uint32_t*)(Clo + o0) = lw;
                pack2(acc[mi][ni][2], acc[mi][ni][3], hw, lw);
                *(uint32_t*)(Chi + o8) = hw;
                *(uint32_t*)(Clo + o8) = lw;
            }
        }
    }
}

// ------- post-seg LN: warp per row of g_x[8192,512], bias + LN -> pair A -----
__global__ void __launch_bounds__(256) row_ln_kernel(
    const float* __restrict__ segb, const float* __restrict__ lng,
    const float* __restrict__ lnb)
{
    const int wid = threadIdx.x >> 5, lane = threadIdx.x & 31;
    const int row = blockIdx.x * 8 + wid;       // row = b*64 + n
    const int n = row & (NPATH - 1);
    const float* xr = g_x + (size_t)row * DIMV;
    const float* bp = segb + (size_t)n * DIMV;

    float v[16], s = 0.f, sq = 0.f;
    #pragma unroll
    for (int i = 0; i < 16; i++) {
        v[i] = xr[lane + 32 * i] + bp[lane + 32 * i];
        s += v[i]; sq += v[i] * v[i];
    }
    #pragma unroll
    for (int o = 16; o > 0; o >>= 1) {
        s  += __shfl_xor_sync(0xffffffffu, s,  o);
        sq += __shfl_xor_sync(0xffffffffu, sq, o);
    }
    float mu  = s * (1.0f / DIMV);
    float rstd = rsqrtf(sq * (1.0f / DIMV) - mu * mu + 1e-5f);
    #pragma unroll
    for (int i = 0; i < 16; i++) {
        int c = lane + 32 * i;
        float o = (v[i] - mu) * rstd * lng[n * DIMV + c] + lnb[n * DIMV + c];
        size_t idx = (size_t)row * DIMV + c;
        __nv_bfloat16 h = __float2bfloat16_rn(o);
        g_ah[idx] = h;
        g_al[idx] = __float2bfloat16_rn(o - __bfloat162float(h));
    }
}

// ------- conv (k=4, t-marching) + bias + silu -> bf16 hi/lo pair A only ------
__global__ void __launch_bounds__(256) conv_silu_kernel(
    const float* __restrict__ cw, const float* __restrict__ cb)
{
    const int b  = blockIdx.x;
    const int t0 = blockIdx.y * 16;
    const int c4 = threadIdx.x * 4;

    float4 w0 = *(const float4*)(cw + (size_t)(c4 + 0) * 4);
    float4 w1 = *(const float4*)(cw + (size_t)(c4 + 1) * 4);
    float4 w2 = *(const float4*)(cw + (size_t)(c4 + 2) * 4);
    float4 w3 = *(const float4*)(cw + (size_t)(c4 + 3) * 4);
    float4 bias = *(const float4*)(cb + c4);

    const float* ubase = g_xz + (size_t)b * SEQ * XZW + c4;
    float4 um3 = make_float4(0,0,0,0), um2 = um3, um1 = um3;
    if (t0 - 3 >= 0) um3 = *(const float4*)(ubase + (size_t)(t0 - 3) * XZW);
    if (t0 - 2 >= 0) um2 = *(const float4*)(ubase + (size_t)(t0 - 2) * XZW);
    if (t0 - 1 >= 0) um1 = *(const float4*)(ubase + (size_t)(t0 - 1) * XZW);

    #pragma unroll
    for (int tt = 0; tt < 16; tt++) {
        const int t = t0 + tt;
        float4 u = *(const float4*)(ubase + (size_t)t * XZW);
        float4 a;
        a.x = bias.x + um3.x*w0.x + um2.x*w0.y + um1.x*w0.z + u.x*w0.w;
        a.y = bias.y + um3.y*w1.x + um2.y*w1.y + um1.y*w1.z + u.y*w1.w;
        a.z = bias.z + um3.z*w2.x + um2.z*w2.y + um1.z*w2.z + u.z*w2.w;
        a.w = bias.w + um3.w*w3.x + um2.w*w3.y + um1.w*w3.z + u.w*w3.w;
        a.x = a.x / (1.0f + __expf(-a.x));
        a.y = a.y / (1.0f + __expf(-a.y));
        a.z = a.z / (1.0f + __expf(-a.z));
        a.w = a.w / (1.0f + __expf(-a.w));
        size_t o = ((size_t)b * SEQ + t) * DINV + c4;
        uint2 hw, lw; cvt_hl(a, hw, lw);
        *(uint2*)(g_ah + o) = hw;
        *(uint2*)(g_al + o) = lw;
        um3 = um2; um2 = um1; um1 = u;
    }
}

// -------- fused dt_proj + softplus + selective scan + gate -> pair B ---------
__global__ void __launch_bounds__(256) scan_kernel(
    const float* __restrict__ A_log, const float* __restrict__ Dp_,
    const float* __restrict__ wdt,   const float* __restrict__ bdt)
{
    const int b = blockIdx.x;
    const int d = blockIdx.y * 256 + threadIdx.x;
    __shared__ float sB[SEQ][NSTATE];
    __shared__ float sC[SEQ][NSTATE];
    __shared__ float sDT[SEQ][DTRV];

    for (int i = threadIdx.x; i < SEQ * 64; i += 256) {
        int t = i >> 6, j = i & 63;
        size_t base = ((size_t)(b * SEQ + t)) * 64 + j;
        float v = 0.f;
        #pragma unroll
        for (int s = 0; s < XSLABS; s++)
            v += g_xdbl[(size_t)s * ROWSZ * 64 + base];
        if (j < 32)       sDT[t][j] = v;
        else if (j < 48)  sB[t][j - 32] = v;
        else              sC[t][j - 48] = v;
    }
    __syncthreads();

    float w[DTRV];
    #pragma unroll
    for (int q = 0; q < DTRV / 4; q++) {
        float4 v = *(const float4*)(wdt + (size_t)d * DTRV + q * 4);
        w[4*q] = v.x; w[4*q+1] = v.y; w[4*q+2] = v.z; w[4*q+3] = v.w;
    }
    const float bdtv = bdt[d];

    float rA[NSTATE];
    #pragma unroll
    for (int n = 0; n < NSTATE; n++) rA[n] = -expf(A_log[(size_t)d * NSTATE + n]);
    const float Dv = Dp_[d];
    float h[NSTATE];
    #pragma unroll
    for (int n = 0; n < NSTATE; n++) h[n] = 0.f;

    const size_t rowbase = (size_t)b * SEQ;
    for (int t = 0; t < SEQ; t++) {
        const size_t row = rowbase + t;
        float dot = bdtv;
        #pragma unroll
        for (int j = 0; j < DTRV; j++) dot += sDT[t][j] * w[j];
        float delta = softplusf(dot);
        float u = __bfloat162float(g_ah[row * DINV + d])
                + __bfloat162float(g_al[row * DINV + d]);
        float du = delta * u;
        float y = 0.f;
        #pragma unroll
        for (int n = 0; n < NSTATE; n++) {
            float dA = __expf(delta * rA[n]);
            h[n] = dA * h[n] + du * sB[t][n];
            y += h[n] * sC[t][n];
        }
        float z = g_xz[row * XZW + DINV + d];
        float silu_z = z / (1.0f + __expf(-z));
        float yv = (y + u * Dv) * silu_z;
        __nv_bfloat16 hb = __float2bfloat16_rn(yv);
        g_bh[row * DINV + d] = hb;
        g_bl[row * DINV + d] = __float2bfloat16_rn(yv - __bfloat162float(hb));
    }
}

// ---------------- final LayerNorm stats ---------------------------------------
__global__ void __launch_bounds__(256) ln_stats_kernel()
{
    const int b = blockIdx.x;
    const float4* xp = (const float4*)(g_x + (size_t)b * HEADK);
    float s = 0.f, sq = 0.f;
    for (int i = threadIdx.x; i < HEADK / 4; i += 256) {
        float4 v = xp[i];
        s  += v.x + v.y + v.z + v.w;
        sq += v.x*v.x + v.y*v.y + v.z*v.z + v.w*v.w;
    }
    __shared__ float rs[256], rq[256];
    rs[threadIdx.x] = s; rq[threadIdx.x] = sq; __syncthreads();
    for (int st = 128; st > 0; st >>= 1) {
        if (threadIdx.x < st) { rs[threadIdx.x] += rs[threadIdx.x + st];
                                rq[threadIdx.x] += rq[threadIdx.x + st]; }
        __syncthreads();
    }
    if (threadIdx.x == 0) {
        float mu  = rs[0] / (float)HEADK;
        float var = rq[0] / (float)HEADK - mu * mu;
        g_stats[b] = make_float2(mu, rsqrtf(var + 1e-5f));
    }
}

// ---------------- head: split-K GEMM (LN fused on A load) --------------------
__global__ void __launch_bounds__(256) head_gemm_kernel(
    const float* __restrict__ lng, const float* __restrict__ lnb,
    const float* __restrict__ hw)
{
    constexpr int BK = 16;
    const int slab = blockIdx.x;
    const int kbeg = slab * (HEADK / HSLABS);
    __shared__ float sX[BK][BATCH];
    __shared__ float sW[BK][NCLS];
    const int tid = threadIdx.x;
    const int tx = tid & 15;
    const int ty = tid >> 4;

    float acc[8][2];
    #pragma unroll
    for (int i = 0; i < 8; i++) { acc[i][0] = 0.f; acc[i][1] = 0.f; }

    for (int k0 = kbeg; k0 < kbeg + HEADK / HSLABS; k0 += BK) {
        #pragma unroll
        for (int l = 0; l < 2; l++) {
            int idx = tid + l * 256;
            int row = idx >> 2, kq = (idx & 3) << 2;
            float2 st = g_stats[row];
            float4 v  = *(const float4*)(g_x + (size_t)row * HEADK + k0 + kq);
            float4 gg = *(const float4*)(lng + k0 + kq);
            float4 bb = *(const float4*)(lnb + k0 + kq);
            sX[kq + 0][row] = (v.x - st.x) * st.y * gg.x + bb.x;
            sX[kq + 1][row] = (v.y - st.x) * st.y * gg.y + bb.y;
            sX[kq + 2][row] = (v.z - st.x) * st.y * gg.z + bb.z;
            sX[kq + 3][row] = (v.w - st.x) * st.y * gg.w + bb.w;
        }
        if (tid < 128) {
            int row = tid >> 2, kq = (tid & 3) << 2;
            float4 v = *(const float4*)(hw + (size_t)row * HEADK + k0 + kq);
            sW[kq + 0][row] = v.x; sW[kq + 1][row] = v.y;
            sW[kq + 2][row] = v.z; sW[kq + 3][row] = v.w;
        }
        __syncthreads();
        #pragma unroll
        for (int kk = 0; kk < BK; kk++) {
            float w0 = sW[kk][tx * 2], w1 = sW[kk][tx * 2 + 1];
            #pragma unroll
            for (int i = 0; i < 8; i++) {
                float a = sX[kk][ty * 8 + i];
                acc[i][0] += a * w0;
                acc[i][1] += a * w1;
            }
        }
        __syncthreads();
    }
    #pragma unroll
    for (int i = 0; i < 8; i++) {
        int m = ty * 8 + i;
        g_hpart[((size_t)slab * BATCH + m) * NCLS + tx * 2 + 0] = acc[i][0];
        g_hpart[((size_t)slab * BATCH + m) * NCLS + tx * 2 + 1] = acc[i][1];
    }
}

__global__ void __launch_bounds__(256) head_reduce_kernel(
    const float* __restrict__ head_b, float* __restrict__ out)
{
    int idx = blockIdx.x * blockDim.x + threadIdx.x;
    if (idx < BATCH * NCLS) {
        float s = head_b[idx & (NCLS - 1)];
        for (int sl = 0; sl < HSLABS; sl++)
            s += g_hpart[(size_t)sl * BATCH * NCLS + idx];
        out[idx] = s;
    }
}

// ---------------- host orchestration -----------------------------------------
extern "C" void kernel_launch(void* const* d_in, const int* in_sizes, int n_in,
                              void* d_out, int out_size)
{
    const float* series    = (const float*)d_in[0];
    const float* seg_w     = (const float*)d_in[1];
    const float* seg_b     = (const float*)d_in[2];
    const float* ln_g      = (const float*)d_in[3];
    const float* ln_b      = (const float*)d_in[4];
    const float* in_proj_w = (const float*)d_in[5];
    const float* conv_w    = (const float*)d_in[6];
    const float* conv_b    = (const float*)d_in[7];
    const float* x_proj_w  = (const float*)d_in[8];
    const float* dt_proj_w = (const float*)d_in[9];
    const float* dt_proj_b = (const float*)d_in[10];
    const float* A_log     = (const float*)d_in[11];
    const float* Dw        = (const float*)d_in[12];
    const float* out_proj_w= (const float*)d_in[13];
    const float* hlng      = (const float*)d_in[14];
    const float* hlnb      = (const float*)d_in[15];
    const float* head_w    = (const float*)d_in[16];
    const float* head_b    = (const float*)d_in[17];
    float* out = (float*)d_out;

    float *px, *pxz, *pxdbl;
    __nv_bfloat16 *pah, *pal, *pbh, *pbl;
    __nv_bfloat16 *pwih, *pwil, *pwxh, *pwxl, *pwoh, *pwol;
    __nv_bfloat16 *pswh, *pswl, *psrh, *psrl;
    cudaGetSymbolAddress((void**)&px,    g_x);
    cudaGetSymbolAddress((void**)&pxz,   g_xz);
    cudaGetSymbolAddress((void**)&pxdbl, g_xdbl);
    cudaGetSymbolAddress((void**)&pah,   g_ah);
    cudaGetSymbolAddress((void**)&pal,   g_al);
    cudaGetSymbolAddress((void**)&pbh,   g_bh);
    cudaGetSymbolAddress((void**)&pbl,   g_bl);
    cudaGetSymbolAddress((void**)&pwih,  g_wih);
    cudaGetSymbolAddress((void**)&pwil,  g_wil);
    cudaGetSymbolAddress((void**)&pwxh,  g_wxh);
    cudaGetSymbolAddress((void**)&pwxl,  g_wxl);
    cudaGetSymbolAddress((void**)&pwoh,  g_woh);
    cudaGetSymbolAddress((void**)&pwol,  g_wol);
    cudaGetSymbolAddress((void**)&pswh,  g_swh);
    cudaGetSymbolAddress((void**)&pswl,  g_swl);
    cudaGetSymbolAddress((void**)&psrh,  g_srh);
    cudaGetSymbolAddress((void**)&psrl,  g_srl);

    const int SMEM128 = 2 * (2*128 + 2*128) * 40 * 2;  // 81920
    const int SMEM64  = 2 * (2*64  + 2*64 ) * 40 * 2;  // 40960
    cudaFuncSetAttribute((const void*)hmma_gemm<128,128,2,4,false,true>,
                         cudaFuncAttributeMaxDynamicSharedMemorySize, SMEM128);
    cudaFuncSetAttribute((const void*)hmma_gemm<128,128,2,4,true,false>,
                         cudaFuncAttributeMaxDynamicSharedMemorySize, SMEM128);
    cudaFuncSetAttribute((const void*)hmma_gemm<64,64,2,4,false,true>,
                         cudaFuncAttributeMaxDynamicSharedMemorySize, SMEM64);

    // 0) one-time prep: everything in ONE launch
    prep_kernel<<<PREP_BLK, 256>>>(in_proj_w, x_proj_w, out_proj_w, seg_w, series);

    // 1) seg linear: batched over 64 pathways -> g_x fp32
    hmma_gemm<128,128,2,4,false,true><<<dim3(DIMV/128, 1, NPATH), 256, SMEM128>>>(
        psrh, psrl, pswh, pswl, px, nullptr, nullptr,
        BATCH, DIMV, PLEN,
        NPATH*PLEN, PLEN, HEADK, PLEN, DIMV*PLEN, (long long)DIMV, 1);

    // 2) bias + per-pathway LN -> pair A
    row_ln_kernel<<<ROWSZ/8, 256>>>(seg_b, ln_g, ln_b);

    for (int dep = 0; dep < DEPTHN; dep++) {
        // 3) in_proj: [8192,512]x[2048,512]^T -> g_xz (fp32)
        hmma_gemm<128,128,2,4,false,true><<<dim3(XZW/128, ROWSZ/128, 1), 256, SMEM128>>>(
            pah, pal, pwih + (size_t)dep * XZW * DIMV,
            pwil + (size_t)dep * XZW * DIMV, pxz, nullptr, nullptr,
            ROWSZ, XZW, DIMV, DIMV, DIMV, XZW, 0, 0, 0, 1);
        // 4) conv + silu -> pair A (bf16 hi/lo)
        conv_silu_kernel<<<dim3(BATCH, SEQ/16), 256>>>(
            conv_w + (size_t)dep * DINV * 4, conv_b + (size_t)dep * DINV);
        // 5) x_proj split-K x2 -> 2 partial slabs
        hmma_gemm<64,64,2,4,false,true><<<dim3(1, ROWSZ/64, XSLABS), 256, SMEM64>>>(
            pah, pal, pwxh + (size_t)dep * 64 * DINV,
            pwxl + (size_t)dep * 64 * DINV, pxdbl, nullptr, nullptr,
            ROWSZ, 64, DINV, DINV, DINV, 64, 0, 0, (long long)ROWSZ * 64, XSLABS);
        // 6) fused dt_proj + softplus + scan + gate -> pair B
        scan_kernel<<<dim3(BATCH, DINV/256), 256>>>(
            A_log + (size_t)dep * DINV * NSTATE, Dw + (size_t)dep * DINV,
            dt_proj_w + (size_t)dep * DINV * DTRV,
            dt_proj_b + (size_t)dep * DINV);
        // 7) out_proj: depth 0 -> pair A only (fp32 g_x dead);
        //    last depth -> fp32 g_x only (pair A dead)
        if (dep == DEPTHN - 1) {
            hmma_gemm<128,128,2,4,false,true><<<dim3(DIMV/128, ROWSZ/128, 1), 256, SMEM128>>>(
                pbh, pbl, pwoh + (size_t)dep * DIMV * DINV,
                pwol + (size_t)dep * DIMV * DINV, px, nullptr, nullptr,
                ROWSZ, DIMV, DINV, DINV, DINV, DIMV, 0, 0, 0, 1);
        } else {
            hmma_gemm<128,128,2,4,true,false><<<dim3(DIMV/128, ROWSZ/128, 1), 256, SMEM128>>>(
                pbh, pbl, pwoh + (size_t)dep * DIMV * DINV,
                pwol + (size_t)dep * DIMV * DINV, px, pah, pal,
                ROWSZ, DIMV, DINV, DINV, DINV, DIMV, 0, 0, 0, 1);
        }
    }

    // 8) final LN stats + head GEMM + deterministic reduce
    ln_stats_kernel<<<BATCH, 256>>>();
    head_gemm_kernel<<<HSLABS, 256>>>(hlng, hlnb, head_w);
    head_reduce_kernel<<<(BATCH*NCLS + 255)/256, 256>>>(head_b, out);
}

// round 17
// speedup vs baseline: 1.0240x; 1.0045x over previous
#include <cuda_runtime.h>
#include <cuda_bf16.h>
#include <math.h>
#include <stdint.h>

// Problem constants
#define BATCH   128
#define NPATH   64
#define PLEN    128
#define DIMV    512
#define NSTATE  16
#define DEPTHN  2
#define DINV    1024
#define DTRV    32
#define NCLS    32
#define SEQ     64
#define ROWSZ   (BATCH*SEQ)        // 8192
#define XZW     (2*DINV)           // 2048
#define HEADK   (NPATH*DIMV)       // 32768
#define HSLABS  64
#define XSLABS  2                  // x_proj split-K factor (4 retired: R7/R15)

// ---------------- scratch (static device globals; no allocation) -------------
__device__ float  g_x[(size_t)ROWSZ*DIMV];
__device__ float  g_xz[(size_t)ROWSZ*XZW];
__device__ float  g_xdbl[(size_t)XSLABS*ROWSZ*64];
__device__ float2 g_stats[BATCH];
__device__ float  g_hpart[(size_t)HSLABS*BATCH*NCLS];
__device__ float  g_rA[(size_t)DEPTHN*DINV*NSTATE];   // precomputed -exp(A_log)
// bf16 hi/lo activation pairs: pair A (x / uc), pair B (scan y)
__device__ __nv_bfloat16 g_ah[(size_t)ROWSZ*DINV];
__device__ __nv_bfloat16 g_al[(size_t)ROWSZ*DINV];
__device__ __nv_bfloat16 g_bh[(size_t)ROWSZ*DINV];
__device__ __nv_bfloat16 g_bl[(size_t)ROWSZ*DINV];
// bf16 hi/lo weight pairs (split once up-front)
__device__ __nv_bfloat16 g_wih[(size_t)DEPTHN*XZW*DIMV];
__device__ __nv_bfloat16 g_wil[(size_t)DEPTHN*XZW*DIMV];
__device__ __nv_bfloat16 g_wxh[(size_t)DEPTHN*64*DINV];
__device__ __nv_bfloat16 g_wxl[(size_t)DEPTHN*64*DINV];
__device__ __nv_bfloat16 g_woh[(size_t)DEPTHN*DIMV*DINV];
__device__ __nv_bfloat16 g_wol[(size_t)DEPTHN*DIMV*DINV];
// seg weights transposed [n][d][p] hi/lo, series hi/lo
__device__ __nv_bfloat16 g_swh[(size_t)NPATH*DIMV*PLEN];
__device__ __nv_bfloat16 g_swl[(size_t)NPATH*DIMV*PLEN];
__device__ __nv_bfloat16 g_srh[(size_t)BATCH*NPATH*PLEN];
__device__ __nv_bfloat16 g_srl[(size_t)BATCH*NPATH*PLEN];

__device__ __forceinline__ float softplusf(float x) {
    return fmaxf(x, 0.0f) + log1pf(expf(-fabsf(x)));
}

__device__ __forceinline__ void cvt_hl(float4 v, uint2& hw, uint2& lw) {
    float f[4] = {v.x, v.y, v.z, v.w};
    unsigned short h[4], l[4];
    #pragma unroll
    for (int i = 0; i < 4; i++) {
        __nv_bfloat16 hb = __float2bfloat16_rn(f[i]);
        h[i] = __bfloat16_as_ushort(hb);
        float r = f[i] - __bfloat162float(hb);
        l[i] = __bfloat16_as_ushort(__float2bfloat16_rn(r));
    }
    hw.x = (uint32_t)h[0] | ((uint32_t)h[1] << 16);
    hw.y = (uint32_t)h[2] | ((uint32_t)h[3] << 16);
    lw.x = (uint32_t)l[0] | ((uint32_t)l[1] << 16);
    lw.y = (uint32_t)l[2] | ((uint32_t)l[3] << 16);
}

__device__ __forceinline__ void pack2(float v0, float v1, uint32_t& hw, uint32_t& lw) {
    __nv_bfloat16 h0 = __float2bfloat16_rn(v0);
    __nv_bfloat16 h1 = __float2bfloat16_rn(v1);
    float r0 = v0 - __bfloat162float(h0), r1 = v1 - __bfloat162float(h1);
    hw = (uint32_t)__bfloat16_as_ushort(h0) | ((uint32_t)__bfloat16_as_ushort(h1) << 16);
    lw = (uint32_t)__bfloat16_as_ushort(__float2bfloat16_rn(r0))
       | ((uint32_t)__bfloat16_as_ushort(__float2bfloat16_rn(r1)) << 16);
}

// ------- ONE prep kernel: weight splits + seg_w transpose + series + rA ------
#define WIN4  (DEPTHN * XZW * DIMV / 4)   // 524288
#define WXN4  (DEPTHN * 64 * DINV / 4)    // 32768
#define WON4  (DEPTHN * DIMV * DINV / 4)  // 262144
#define SPLIT3_N4   (WIN4 + WXN4 + WON4)              // 819200
#define SPLIT3_BLK  (SPLIT3_N4 / 256)                 // 3200
#define TRANS_BLK   ((DIMV/32) * (PLEN/32) * NPATH)   // 4096
#define SER_N4      (BATCH * NPATH * PLEN / 4)        // 262144
#define SER_BLK     (SER_N4 / 256)                    // 1024
#define RA_N        (DEPTHN * DINV * NSTATE)          // 32768
#define RA_BLK      (RA_N / 256)                      // 128
#define PREP_BLK    (SPLIT3_BLK + TRANS_BLK + SER_BLK + RA_BLK)

__global__ void __launch_bounds__(256) prep_kernel(
    const float* __restrict__ wi, const float* __restrict__ wx,
    const float* __restrict__ wo, const float* __restrict__ segw,
    const float* __restrict__ series, const float* __restrict__ A_log)
{
    const int blk = blockIdx.x;
    if (blk < SPLIT3_BLK) {
        int i = blk * 256 + threadIdx.x;
        const float* src; __nv_bfloat16 *hi, *lo; int idx;
        if (i < WIN4)                    { src = wi; hi = g_wih; lo = g_wil; idx = i; }
        else if (i < WIN4 + WXN4)        { src = wx; hi = g_wxh; lo = g_wxl; idx = i - WIN4; }
        else                             { src = wo; hi = g_woh; lo = g_wol; idx = i - WIN4 - WXN4; }
        float4 v = ((const float4*)src)[idx];
        uint2 hw, lw; cvt_hl(v, hw, lw);
        ((uint2*)hi)[idx] = hw;
        ((uint2*)lo)[idx] = lw;
    } else if (blk < SPLIT3_BLK + TRANS_BLK) {
        __shared__ float tile[32][33];
        const int i = blk - SPLIT3_BLK;
        const int d0 = (i & 15) * 32, p0 = ((i >> 4) & 3) * 32, n = i >> 6;
        const int tx = threadIdx.x & 31, ty = threadIdx.x >> 5;
        #pragma unroll
        for (int j = 0; j < 4; j++) {
            int p = p0 + ty + j * 8;
            tile[ty + j * 8][tx] =
                segw[(size_t)n * PLEN * DIMV + (size_t)p * DIMV + d0 + tx];
        }
        __syncthreads();
        #pragma unroll
        for (int j = 0; j < 4; j++) {
            int d = d0 + ty + j * 8;
            float v = tile[tx][ty + j * 8];
            __nv_bfloat16 h = __float2bfloat16_rn(v);
            size_t o = (size_t)n * DIMV * PLEN + (size_t)d * PLEN + p0 + tx;
            g_swh[o] = h;
            g_swl[o] = __float2bfloat16_rn(v - __bfloat162float(h));
        }
    } else if (blk < SPLIT3_BLK + TRANS_BLK + SER_BLK) {
        int idx = (blk - SPLIT3_BLK - TRANS_BLK) * 256 + threadIdx.x;
        float4 v = ((const float4*)series)[idx];
        uint2 hw, lw; cvt_hl(v, hw, lw);
        ((uint2*)g_srh)[idx] = hw;
        ((uint2*)g_srl)[idx] = lw;
    } else {
        int idx = (blk - SPLIT3_BLK - TRANS_BLK - SER_BLK) * 256 + threadIdx.x;
        g_rA[idx] = -expf(A_log[idx]);
    }
}

__device__ __forceinline__ void mma16816(float* c, const uint32_t* a, const uint32_t* b) {
    asm volatile(
        "mma.sync.aligned.m16n8k16.row.col.f32.bf16.bf16.f32 "
        "{%0,%1,%2,%3}, {%4,%5,%6,%7}, {%8,%9}, {%0,%1,%2,%3};"
        : "+f"(c[0]), "+f"(c[1]), "+f"(c[2]), "+f"(c[3])
        : "r"(a[0]), "r"(a[1]), "r"(a[2]), "r"(a[3]), "r"(b[0]), "r"(b[1]));
}
__device__ __forceinline__ void ldsm4(uint32_t* r, uint32_t addr) {
    asm volatile("ldmatrix.sync.aligned.m8n8.x4.shared.b16 {%0,%1,%2,%3}, [%4];"
        : "=r"(r[0]), "=r"(r[1]), "=r"(r[2]), "=r"(r[3]) : "r"(addr));
}
__device__ __forceinline__ void cp16(uint32_t dst, const void* src) {
    asm volatile("cp.async.cg.shared.global [%0], [%1], 16;" :: "r"(dst), "l"(src));
}
__device__ __forceinline__ void cp_commit() {
    asm volatile("cp.async.commit_group;" ::: "memory");
}
template<int N>
__device__ __forceinline__ void cp_wait() {
    asm volatile("cp.async.wait_group %0;" :: "n"(N) : "memory");
}

// =============== HMMA bf16x3 GEMM (ldmatrix + cp.async pipeline) =============
template<int BM, int BN, int WM, int WN, bool WSPLIT, bool WRITEC>
__global__ void __launch_bounds__(256, 2) hmma_gemm(
    const __nv_bfloat16* __restrict__ Ah, const __nv_bfloat16* __restrict__ Al,
    const __nv_bfloat16* __restrict__ Wh, const __nv_bfloat16* __restrict__ Wl,
    float* __restrict__ C, __nv_bfloat16* __restrict__ Chi,
    __nv_bfloat16* __restrict__ Clo, int M, int N, int K,
    int lda, int ldb, int ldc, int aZ, int wZ, long long cZ, int nsplit)
{
    constexpr int BK = 32, SA = 40;
    constexpr int WTM = BM / WM, WTN = BN / WN;
    constexpr int MF = WTM / 16, NF = WTN / 8;
    static_assert(WM * WN == 8, "8 warps");
    static_assert(NF % 2 == 0, "NF even for paired ldmatrix");
    constexpr int AOFF = 0, ALOFF = BM * SA, WOFF = 2 * BM * SA,
                  WLOFF = 2 * BM * SA + BN * SA;
    constexpr int STG = (2 * BM + 2 * BN) * SA;

    extern __shared__ __nv_bfloat16 smem[];
    uint32_t sbase;
    asm("{ .reg .u64 t; cvta.to.shared.u64 t, %1; cvt.u32.u64 %0, t; }"
        : "=r"(sbase) : "l"(smem));

    const int tid = threadIdx.x, lane = tid & 31, wid = tid >> 5;
    const int warpM = wid % WM, warpN = wid / WM;
    const int m0 = blockIdx.y * BM, n0 = blockIdx.x * BN;
    const int z = blockIdx.z;
    Ah += (size_t)z * aZ;  Al += (size_t)z * aZ;
    Wh += (size_t)z * wZ;  Wl += (size_t)z * wZ;
    C  += (size_t)z * cZ;
    const int Keff  = K / nsplit;
    const int kbase = (nsplit > 1) ? z * Keff : 0;
    const int g = lane >> 2, c2 = (lane & 3) * 2;
    const int mbase = warpM * WTM, nbase = warpN * WTN;

    const int a_row = (lane & 7) | (((lane >> 3) & 1) << 3);
    const int a_kof = ((lane >> 4) & 1) * 8;
    const int b_row = (lane & 7) | (((lane >> 4) & 1) << 3);
    const int b_kof = ((lane >> 3) & 1) * 8;

    float acc[MF][NF][4];
    #pragma unroll
    for (int mi = 0; mi < MF; mi++)
        #pragma unroll
        for (int ni = 0; ni < NF; ni++)
            #pragma unroll
            for (int q = 0; q < 4; q++) acc[mi][ni][q] = 0.f;

    const int NC = Keff / BK;

    auto load_chunk = [&](int c, int s) {
        const int kc = kbase + c * BK;
        const uint32_t st = sbase + (uint32_t)s * STG * 2;
        #pragma unroll
        for (int it = 0; it < (BM * 4 + 255) / 256; it++) {
            int i = tid + it * 256;
            if ((BM * 4) % 256 == 0 || i < BM * 4) {
                int r = i >> 2, q = i & 3;
                uint32_t d = st + (uint32_t)r * 80 + q * 16;
                const size_t go = (size_t)(m0 + r) * lda + kc + q * 8;
                cp16(d + AOFF * 2,  Ah + go);
                cp16(d + ALOFF * 2, Al + go);
            }
        }
        #pragma unroll
        for (int it = 0; it < (BN * 4 + 255) / 256; it++) {
            int i = tid + it * 256;
            if ((BN * 4) % 256 == 0 || i < BN * 4) {
                int r = i >> 2, q = i & 3;
                uint32_t d = st + (uint32_t)r * 80 + q * 16;
                const size_t go = (size_t)(n0 + r) * ldb + kc + q * 8;
                cp16(d + WOFF * 2,  Wh + go);
                cp16(d + WLOFF * 2, Wl + go);
            }
        }
    };

    load_chunk(0, 0);
    cp_commit();

    for (int c = 0; c < NC; c++) {
        const int s = c & 1;
        if (c + 1 < NC) {
            load_chunk(c + 1, (c + 1) & 1);
            cp_commit();
            cp_wait<1>();
        } else {
            cp_wait<0>();
        }
        __syncthreads();

        const uint32_t sb  = sbase + (uint32_t)s * STG * 2;
        const uint32_t pAh = sb + AOFF * 2,  pAl = sb + ALOFF * 2;
        const uint32_t pWh = sb + WOFF * 2,  pWl = sb + WLOFF * 2;

        #pragma unroll
        for (int ks = 0; ks < BK; ks += 16) {
            uint32_t ah[MF][4], al[MF][4], bh[NF][2], bl[NF][2];
            #pragma unroll
            for (int mi = 0; mi < MF; mi++)
                ldsm4(ah[mi], pAh + ((uint32_t)(mbase + mi * 16 + a_row) * SA
                                     + ks + a_kof) * 2);
            #pragma unroll
            for (int ni = 0; ni < NF; ni += 2) {
                uint32_t t[4];
                ldsm4(t, pWh + ((uint32_t)(nbase + ni * 8 + b_row) * SA
                                + ks + b_kof) * 2);
                bh[ni][0] = t[0]; bh[ni][1] = t[1];
                bh[ni + 1][0] = t[2]; bh[ni + 1][1] = t[3];
            }
            #pragma unroll
            for (int mi = 0; mi < MF; mi++)
                #pragma unroll
                for (int ni = 0; ni < NF; ni++)
                    mma16816(acc[mi][ni], ah[mi], bh[ni]);
            #pragma unroll
            for (int ni = 0; ni < NF; ni += 2) {
                uint32_t t[4];
                ldsm4(t, pWl + ((uint32_t)(nbase + ni * 8 + b_row) * SA
                                + ks + b_kof) * 2);
                bl[ni][0] = t[0]; bl[ni][1] = t[1];
                bl[ni + 1][0] = t[2]; bl[ni + 1][1] = t[3];
            }
            #pragma unroll
            for (int mi = 0; mi < MF; mi++)
                #pragma unroll
                for (int ni = 0; ni < NF; ni++)
                    mma16816(acc[mi][ni], ah[mi], bl[ni]);
            #pragma unroll
            for (int mi = 0; mi < MF; mi++)
                ldsm4(al[mi], pAl + ((uint32_t)(mbase + mi * 16 + a_row) * SA
                                     + ks + a_kof) * 2);
            #pragma unroll
            for (int mi = 0; mi < MF; mi++)
                #pragma unroll
                for (int ni = 0; ni < NF; ni++)
                    mma16816(acc[mi][ni], al[mi], bh[ni]);
        }
        __syncthreads();
    }

    #pragma unroll
    for (int mi = 0; mi < MF; mi++) {
        int row = m0 + mbase + mi * 16 + g;
        #pragma unroll
        for (int ni = 0; ni < NF; ni++) {
            int col = n0 + nbase + ni * 8 + c2;
            size_t o0 = (size_t)row * ldc + col;
            size_t o8 = (size_t)(row + 8) * ldc + col;
            if (WRITEC) {
                *(float2*)(C + o0) = make_float2(acc[mi][ni][0], acc[mi][ni][1]);
                *(float2*)(C + o8) = make_float2(acc[mi][ni][2], acc[mi][ni][3]);
            }
            if (WSPLIT) {
                uint32_t hw, lw;
                pack2(acc[mi][ni][0], acc[mi][ni][1], hw, lw);
                *(uint32_t*)(Chi + o0) = hw;
                *(uint32_t*)(Clo + o0) = lw;
                pack2(acc[mi][ni][2], acc[mi][ni][3], hw, lw);
                *(uint32_t*)(Chi + o8) = hw;
                *(uint32_t*)(Clo + o8) = lw;
            }
        }
    }
}

// ------- post-seg LN: warp per row of g_x[8192,512], bias + LN -> pair A -----
__global__ void __launch_bounds__(256) row_ln_kernel(
    const float* __restrict__ segb, const float* __restrict__ lng,
    const float* __restrict__ lnb)
{
    const int wid = threadIdx.x >> 5, lane = threadIdx.x & 31;
    const int row = blockIdx.x * 8 + wid;       // row = b*64 + n
    const int n = row & (NPATH - 1);
    const float* xr = g_x + (size_t)row * DIMV;
    const float* bp = segb + (size_t)n * DIMV;

    float v[16], s = 0.f, sq = 0.f;
    #pragma unroll
    for (int i = 0; i < 16; i++) {
        v[i] = xr[lane + 32 * i] + bp[lane + 32 * i];
        s += v[i]; sq += v[i] * v[i];
    }
    #pragma unroll
    for (int o = 16; o > 0; o >>= 1) {
        s  += __shfl_xor_sync(0xffffffffu, s,  o);
        sq += __shfl_xor_sync(0xffffffffu, sq, o);
    }
    float mu  = s * (1.0f / DIMV);
    float rstd = rsqrtf(sq * (1.0f / DIMV) - mu * mu + 1e-5f);
    #pragma unroll
    for (int i = 0; i < 16; i++) {
        int c = lane + 32 * i;
        float o = (v[i] - mu) * rstd * lng[n * DIMV + c] + lnb[n * DIMV + c];
        size_t idx = (size_t)row * DIMV + c;
        __nv_bfloat16 h = __float2bfloat16_rn(o);
        g_ah[idx] = h;
        g_al[idx] = __float2bfloat16_rn(o - __bfloat162float(h));
    }
}

// ------- conv (k=4, t-marching) + bias + silu -> bf16 hi/lo pair A only ------
__global__ void __launch_bounds__(256) conv_silu_kernel(
    const float* __restrict__ cw, const float* __restrict__ cb)
{
    const int b  = blockIdx.x;
    const int t0 = blockIdx.y * 16;
    const int c4 = threadIdx.x * 4;

    float4 w0 = *(const float4*)(cw + (size_t)(c4 + 0) * 4);
    float4 w1 = *(const float4*)(cw + (size_t)(c4 + 1) * 4);
    float4 w2 = *(const float4*)(cw + (size_t)(c4 + 2) * 4);
    float4 w3 = *(const float4*)(cw + (size_t)(c4 + 3) * 4);
    float4 bias = *(const float4*)(cb + c4);

    const float* ubase = g_xz + (size_t)b * SEQ * XZW + c4;
    float4 um3 = make_float4(0,0,0,0), um2 = um3, um1 = um3;
    if (t0 - 3 >= 0) um3 = *(const float4*)(ubase + (size_t)(t0 - 3) * XZW);
    if (t0 - 2 >= 0) um2 = *(const float4*)(ubase + (size_t)(t0 - 2) * XZW);
    if (t0 - 1 >= 0) um1 = *(const float4*)(ubase + (size_t)(t0 - 1) * XZW);

    #pragma unroll
    for (int tt = 0; tt < 16; tt++) {
        const int t = t0 + tt;
        float4 u = *(const float4*)(ubase + (size_t)t * XZW);
        float4 a;
        a.x = bias.x + um3.x*w0.x + um2.x*w0.y + um1.x*w0.z + u.x*w0.w;
        a.y = bias.y + um3.y*w1.x + um2.y*w1.y + um1.y*w1.z + u.y*w1.w;
        a.z = bias.z + um3.z*w2.x + um2.z*w2.y + um1.z*w2.z + u.z*w2.w;
        a.w = bias.w + um3.w*w3.x + um2.w*w3.y + um1.w*w3.z + u.w*w3.w;
        a.x = a.x / (1.0f + __expf(-a.x));
        a.y = a.y / (1.0f + __expf(-a.y));
        a.z = a.z / (1.0f + __expf(-a.z));
        a.w = a.w / (1.0f + __expf(-a.w));
        size_t o = ((size_t)b * SEQ + t) * DINV + c4;
        uint2 hw, lw; cvt_hl(a, hw, lw);
        *(uint2*)(g_ah + o) = hw;
        *(uint2*)(g_al + o) = lw;
        um3 = um2; um2 = um1; um1 = u;
    }
}

// -------- fused dt_proj + softplus + selective scan + gate -> pair B ---------
// rA loaded from precomputed table (same expf, computed once in prep).
__global__ void __launch_bounds__(256) scan_kernel(
    const float* __restrict__ rAtab, const float* __restrict__ Dp_,
    const float* __restrict__ wdt,   const float* __restrict__ bdt)
{
    const int b = blockIdx.x;
    const int d = blockIdx.y * 256 + threadIdx.x;
    __shared__ float sB[SEQ][NSTATE];
    __shared__ float sC[SEQ][NSTATE];
    __shared__ float sDT[SEQ][DTRV];

    for (int i = threadIdx.x; i < SEQ * 64; i += 256) {
        int t = i >> 6, j = i & 63;
        size_t base = ((size_t)(b * SEQ + t)) * 64 + j;
        float v = 0.f;
        #pragma unroll
        for (int s = 0; s < XSLABS; s++)
            v += g_xdbl[(size_t)s * ROWSZ * 64 + base];
        if (j < 32)       sDT[t][j] = v;
        else if (j < 48)  sB[t][j - 32] = v;
        else              sC[t][j - 48] = v;
    }
    __syncthreads();

    float w[DTRV];
    #pragma unroll
    for (int q = 0; q < DTRV / 4; q++) {
        float4 v = *(const float4*)(wdt + (size_t)d * DTRV + q * 4);
        w[4*q] = v.x; w[4*q+1] = v.y; w[4*q+2] = v.z; w[4*q+3] = v.w;
    }
    const float bdtv = bdt[d];

    float rA[NSTATE];
    #pragma unroll
    for (int q = 0; q < NSTATE / 4; q++) {
        float4 v = *(const float4*)(rAtab + (size_t)d * NSTATE + q * 4);
        rA[4*q] = v.x; rA[4*q+1] = v.y; rA[4*q+2] = v.z; rA[4*q+3] = v.w;
    }
    const float Dv = Dp_[d];
    float h[NSTATE];
    #pragma unroll
    for (int n = 0; n < NSTATE; n++) h[n] = 0.f;

    const size_t rowbase = (size_t)b * SEQ;
    for (int t = 0; t < SEQ; t++) {
        const size_t row = rowbase + t;
        float dot = bdtv;
        #pragma unroll
        for (int j = 0; j < DTRV; j++) dot += sDT[t][j] * w[j];
        float delta = softplusf(dot);
        float u = __bfloat162float(g_ah[row * DINV + d])
                + __bfloat162float(g_al[row * DINV + d]);
        float du = delta * u;
        float y = 0.f;
        #pragma unroll
        for (int n = 0; n < NSTATE; n++) {
            float dA = __expf(delta * rA[n]);
            h[n] = dA * h[n] + du * sB[t][n];
            y += h[n] * sC[t][n];
        }
        float z = g_xz[row * XZW + DINV + d];
        float silu_z = z / (1.0f + __expf(-z));
        float yv = (y + u * Dv) * silu_z;
        __nv_bfloat16 hb = __float2bfloat16_rn(yv);
        g_bh[row * DINV + d] = hb;
        g_bl[row * DINV + d] = __float2bfloat16_rn(yv - __bfloat162float(hb));
    }
}

// ---------------- final LayerNorm stats ---------------------------------------
__global__ void __launch_bounds__(256) ln_stats_kernel()
{
    const int b = blockIdx.x;
    const float4* xp = (const float4*)(g_x + (size_t)b * HEADK);
    float s = 0.f, sq = 0.f;
    for (int i = threadIdx.x; i < HEADK / 4; i += 256) {
        float4 v = xp[i];
        s  += v.x + v.y + v.z + v.w;
        sq += v.x*v.x + v.y*v.y + v.z*v.z + v.w*v.w;
    }
    __shared__ float rs[256], rq[256];
    rs[threadIdx.x] = s; rq[threadIdx.x] = sq; __syncthreads();
    for (int st = 128; st > 0; st >>= 1) {
        if (threadIdx.x < st) { rs[threadIdx.x] += rs[threadIdx.x + st];
                                rq[threadIdx.x] += rq[threadIdx.x + st]; }
        __syncthreads();
    }
    if (threadIdx.x == 0) {
        float mu  = rs[0] / (float)HEADK;
        float var = rq[0] / (float)HEADK - mu * mu;
        g_stats[b] = make_float2(mu, rsqrtf(var + 1e-5f));
    }
}

// ---------------- head: split-K GEMM (LN fused on A load) --------------------
__global__ void __launch_bounds__(256) head_gemm_kernel(
    const float* __restrict__ lng, const float* __restrict__ lnb,
    const float* __restrict__ hw)
{
    constexpr int BK = 16;
    const int slab = blockIdx.x;
    const int kbeg = slab * (HEADK / HSLABS);
    __shared__ float sX[BK][BATCH];
    __shared__ float sW[BK][NCLS];
    const int tid = threadIdx.x;
    const int tx = tid & 15;
    const int ty = tid >> 4;

    float acc[8][2];
    #pragma unroll
    for (int i = 0; i < 8; i++) { acc[i][0] = 0.f; acc[i][1] = 0.f; }

    for (int k0 = kbeg; k0 < kbeg + HEADK / HSLABS; k0 += BK) {
        #pragma unroll
        for (int l = 0; l < 2; l++) {
            int idx = tid + l * 256;
            int row = idx >> 2, kq = (idx & 3) << 2;
            float2 st = g_stats[row];
            float4 v  = *(const float4*)(g_x + (size_t)row * HEADK + k0 + kq);
            float4 gg = *(const float4*)(lng + k0 + kq);
            float4 bb = *(const float4*)(lnb + k0 + kq);
            sX[kq + 0][row] = (v.x - st.x) * st.y * gg.x + bb.x;
            sX[kq + 1][row] = (v.y - st.x) * st.y * gg.y + bb.y;
            sX[kq + 2][row] = (v.z - st.x) * st.y * gg.z + bb.z;
            sX[kq + 3][row] = (v.w - st.x) * st.y * gg.w + bb.w;
        }
        if (tid < 128) {
            int row = tid >> 2, kq = (tid & 3) << 2;
            float4 v = *(const float4*)(hw + (size_t)row * HEADK + k0 + kq);
            sW[kq + 0][row] = v.x; sW[kq + 1][row] = v.y;
            sW[kq + 2][row] = v.z; sW[kq + 3][row] = v.w;
        }
        __syncthreads();
        #pragma unroll
        for (int kk = 0; kk < BK; kk++) {
            float w0 = sW[kk][tx * 2], w1 = sW[kk][tx * 2 + 1];
            #pragma unroll
            for (int i = 0; i < 8; i++) {
                float a = sX[kk][ty * 8 + i];
                acc[i][0] += a * w0;
                acc[i][1] += a * w1;
            }
        }
        __syncthreads();
    }
    #pragma unroll
    for (int i = 0; i < 8; i++) {
        int m = ty * 8 + i;
        g_hpart[((size_t)slab * BATCH + m) * NCLS + tx * 2 + 0] = acc[i][0];
        g_hpart[((size_t)slab * BATCH + m) * NCLS + tx * 2 + 1] = acc[i][1];
    }
}

__global__ void __launch_bounds__(256) head_reduce_kernel(
    const float* __restrict__ head_b, float* __restrict__ out)
{
    int idx = blockIdx.x * blockDim.x + threadIdx.x;
    if (idx < BATCH * NCLS) {
        float s = head_b[idx & (NCLS - 1)];
        for (int sl = 0; sl < HSLABS; sl++)
            s += g_hpart[(size_t)sl * BATCH * NCLS + idx];
        out[idx] = s;
    }
}

// ---------------- host orchestration -----------------------------------------
extern "C" void kernel_launch(void* const* d_in, const int* in_sizes, int n_in,
                              void* d_out, int out_size)
{
    const float* series    = (const float*)d_in[0];
    const float* seg_w     = (const float*)d_in[1];
    const float* seg_b     = (const float*)d_in[2];
    const float* ln_g      = (const float*)d_in[3];
    const float* ln_b      = (const float*)d_in[4];
    const float* in_proj_w = (const float*)d_in[5];
    const float* conv_w    = (const float*)d_in[6];
    const float* conv_b    = (const float*)d_in[7];
    const float* x_proj_w  = (const float*)d_in[8];
    const float* dt_proj_w = (const float*)d_in[9];
    const float* dt_proj_b = (const float*)d_in[10];
    const float* A_log     = (const float*)d_in[11];
    const float* Dw        = (const float*)d_in[12];
    const float* out_proj_w= (const float*)d_in[13];
    const float* hlng      = (const float*)d_in[14];
    const float* hlnb      = (const float*)d_in[15];
    const float* head_w    = (const float*)d_in[16];
    const float* head_b    = (const float*)d_in[17];
    float* out = (float*)d_out;

    float *px, *pxz, *pxdbl, *prA;
    __nv_bfloat16 *pah, *pal, *pbh, *pbl;
    __nv_bfloat16 *pwih, *pwil, *pwxh, *pwxl, *pwoh, *pwol;
    __nv_bfloat16 *pswh, *pswl, *psrh, *psrl;
    cudaGetSymbolAddress((void**)&px,    g_x);
    cudaGetSymbolAddress((void**)&pxz,   g_xz);
    cudaGetSymbolAddress((void**)&pxdbl, g_xdbl);
    cudaGetSymbolAddress((void**)&prA,   g_rA);
    cudaGetSymbolAddress((void**)&pah,   g_ah);
    cudaGetSymbolAddress((void**)&pal,   g_al);
    cudaGetSymbolAddress((void**)&pbh,   g_bh);
    cudaGetSymbolAddress((void**)&pbl,   g_bl);
    cudaGetSymbolAddress((void**)&pwih,  g_wih);
    cudaGetSymbolAddress((void**)&pwil,  g_wil);
    cudaGetSymbolAddress((void**)&pwxh,  g_wxh);
    cudaGetSymbolAddress((void**)&pwxl,  g_wxl);
    cudaGetSymbolAddress((void**)&pwoh,  g_woh);
    cudaGetSymbolAddress((void**)&pwol,  g_wol);
    cudaGetSymbolAddress((void**)&pswh,  g_swh);
    cudaGetSymbolAddress((void**)&pswl,  g_swl);
    cudaGetSymbolAddress((void**)&psrh,  g_srh);
    cudaGetSymbolAddress((void**)&psrl,  g_srl);

    const int SMEM128 = 2 * (2*128 + 2*128) * 40 * 2;  // 81920
    const int SMEM64  = 2 * (2*64  + 2*64 ) * 40 * 2;  // 40960
    cudaFuncSetAttribute((const void*)hmma_gemm<128,128,2,4,false,true>,
                         cudaFuncAttributeMaxDynamicSharedMemorySize, SMEM128);
    cudaFuncSetAttribute((const void*)hmma_gemm<128,128,2,4,true,false>,
                         cudaFuncAttributeMaxDynamicSharedMemorySize, SMEM128);
    cudaFuncSetAttribute((const void*)hmma_gemm<64,64,2,4,false,true>,
                         cudaFuncAttributeMaxDynamicSharedMemorySize, SMEM64);

    // 0) one-time prep: everything in ONE launch (incl. rA table)
    prep_kernel<<<PREP_BLK, 256>>>(in_proj_w, x_proj_w, out_proj_w,
                                   seg_w, series, A_log);

    // 1) seg linear: batched over 64 pathways -> g_x fp32
    hmma_gemm<128,128,2,4,false,true><<<dim3(DIMV/128, 1, NPATH), 256, SMEM128>>>(
        psrh, psrl, pswh, pswl, px, nullptr, nullptr,
        BATCH, DIMV, PLEN,
        NPATH*PLEN, PLEN, HEADK, PLEN, DIMV*PLEN, (long long)DIMV, 1);

    // 2) bias + per-pathway LN -> pair A
    row_ln_kernel<<<ROWSZ/8, 256>>>(seg_b, ln_g, ln_b);

    for (int dep = 0; dep < DEPTHN; dep++) {
        // 3) in_proj: [8192,512]x[2048,512]^T -> g_xz (fp32)
        hmma_gemm<128,128,2,4,false,true><<<dim3(XZW/128, ROWSZ/128, 1), 256, SMEM128>>>(
            pah, pal, pwih + (size_t)dep * XZW * DIMV,
            pwil + (size_t)dep * XZW * DIMV, pxz, nullptr, nullptr,
            ROWSZ, XZW, DIMV, DIMV, DIMV, XZW, 0, 0, 0, 1);
        // 4) conv + silu -> pair A (bf16 hi/lo)
        conv_silu_kernel<<<dim3(BATCH, SEQ/16), 256>>>(
            conv_w + (size_t)dep * DINV * 4, conv_b + (size_t)dep * DINV);
        // 5) x_proj split-K x2 -> 2 partial slabs
        hmma_gemm<64,64,2,4,false,true><<<dim3(1, ROWSZ/64, XSLABS), 256, SMEM64>>>(
            pah, pal, pwxh + (size_t)dep * 64 * DINV,
            pwxl + (size_t)dep * 64 * DINV, pxdbl, nullptr, nullptr,
            ROWSZ, 64, DINV, DINV, DINV, 64, 0, 0, (long long)ROWSZ * 64, XSLABS);
        // 6) fused dt_proj + softplus + scan + gate -> pair B
        scan_kernel<<<dim3(BATCH, DINV/256), 256>>>(
            prA + (size_t)dep * DINV * NSTATE, Dw + (size_t)dep * DINV,
            dt_proj_w + (size_t)dep * DINV * DTRV,
            dt_proj_b + (size_t)dep * DINV);
        // 7) out_proj: depth 0 -> pair A only (fp32 g_x dead);
        //    last depth -> fp32 g_x only (pair A dead)
        if (dep == DEPTHN - 1) {
            hmma_gemm<128,128,2,4,false,true><<<dim3(DIMV/128, ROWSZ/128, 1), 256, SMEM128>>>(
                pbh, pbl, pwoh + (size_t)dep * DIMV * DINV,
                pwol + (size_t)dep * DIMV * DINV, px, nullptr, nullptr,
                ROWSZ, DIMV, DINV, DINV, DINV, DIMV, 0, 0, 0, 1);
        } else {
            hmma_gemm<128,128,2,4,true,false><<<dim3(DIMV/128, ROWSZ/128, 1), 256, SMEM128>>>(
                pbh, pbl, pwoh + (size_t)dep * DIMV * DINV,
                pwol + (size_t)dep * DIMV * DINV, px, pah, pal,
                ROWSZ, DIMV, DINV, DINV, DINV, DIMV, 0, 0, 0, 1);
        }
    }

    // 8) final LN stats + head GEMM + deterministic reduce
    ln_stats_kernel<<<BATCH, 256>>>();
    head_gemm_kernel<<<HSLABS, 256>>>(hlng, hlnb, head_w);
    head_reduce_kernel<<<(BATCH*NCLS + 255)/256, 256>>>(head_b, out);
}